// round 2
// baseline (speedup 1.0000x reference)
#include <cuda_runtime.h>

// Problem constants (fixed by the dataset)
static constexpr int S_  = 2048;
static constexpr int B_  = 2;
static constexpr int D_  = 1024;
static constexpr int H_  = 16;
static constexpr int DK_ = 64;
static constexpr int R_  = S_ * B_;   // 4096 token rows

// Scratch (device globals; no allocation allowed)
__device__ float g_Q[(size_t)B_ * H_ * S_ * DK_];   // (B,H,S,dk)
__device__ float g_K[(size_t)B_ * H_ * S_ * DK_];
__device__ float g_V[(size_t)B_ * H_ * S_ * DK_];
__device__ float g_ctx[(size_t)R_ * D_];            // (S,B,D)

// ---------------------------------------------------------------------------
// GEMM (NT): C[M,N] = X[M,K] @ W[N,K]^T   with M=4096, N=K=1024
// which = 0/1/2 : write to g_Q/g_K/g_V in (B,H,S,dk) layout, scaled
// which = 3     : X := g_ctx, write plain row-major to Cext with bias
// ---------------------------------------------------------------------------
__global__ __launch_bounds__(256) void gemm_nt_kernel(
    const float* __restrict__ X, const float* __restrict__ W,
    float* __restrict__ Cext, const float* __restrict__ bias,
    float scale, int which)
{
    constexpr int K = D_;
    constexpr int BM = 128, BN = 128, BK = 16;
    __shared__ float As[BK][BM + 4];
    __shared__ float Bs[BK][BN + 4];

    const float* Xp = (which == 3) ? (const float*)g_ctx : X;

    const int tid = threadIdx.x;
    const int m0 = blockIdx.y * BM;
    const int n0 = blockIdx.x * BN;
    const int tx = tid & 15, ty = tid >> 4;

    float acc[8][8];
#pragma unroll
    for (int i = 0; i < 8; ++i)
#pragma unroll
        for (int j = 0; j < 8; ++j) acc[i][j] = 0.f;

    for (int k0 = 0; k0 < K; k0 += BK) {
#pragma unroll
        for (int it = 0; it < 2; ++it) {
            int idx = tid + it * 256;
            int row = idx >> 2;
            int c4  = (idx & 3) * 4;
            float4 va = *(const float4*)&Xp[(size_t)(m0 + row) * K + k0 + c4];
            As[c4 + 0][row] = va.x; As[c4 + 1][row] = va.y;
            As[c4 + 2][row] = va.z; As[c4 + 3][row] = va.w;
            float4 vb = *(const float4*)&W[(size_t)(n0 + row) * K + k0 + c4];
            Bs[c4 + 0][row] = vb.x; Bs[c4 + 1][row] = vb.y;
            Bs[c4 + 2][row] = vb.z; Bs[c4 + 3][row] = vb.w;
        }
        __syncthreads();
#pragma unroll
        for (int k = 0; k < BK; ++k) {
            float a[8], b[8];
            *(float4*)&a[0] = *(const float4*)&As[k][ty * 4];
            *(float4*)&a[4] = *(const float4*)&As[k][64 + ty * 4];
            *(float4*)&b[0] = *(const float4*)&Bs[k][tx * 4];
            *(float4*)&b[4] = *(const float4*)&Bs[k][64 + tx * 4];
#pragma unroll
            for (int i = 0; i < 8; ++i)
#pragma unroll
                for (int j = 0; j < 8; ++j)
                    acc[i][j] = fmaf(a[i], b[j], acc[i][j]);
        }
        __syncthreads();
    }

    float* C = (which == 0) ? g_Q : (which == 1) ? g_K : (which == 2) ? g_V : Cext;

#pragma unroll
    for (int ih = 0; ih < 2; ++ih) {
#pragma unroll
        for (int i = 0; i < 4; ++i) {
            int m = m0 + ih * 64 + ty * 4 + i;
#pragma unroll
            for (int jh = 0; jh < 2; ++jh) {
                int n = n0 + jh * 64 + tx * 4;
                float4 r;
                r.x = acc[ih * 4 + i][jh * 4 + 0] * scale;
                r.y = acc[ih * 4 + i][jh * 4 + 1] * scale;
                r.z = acc[ih * 4 + i][jh * 4 + 2] * scale;
                r.w = acc[ih * 4 + i][jh * 4 + 3] * scale;
                if (which <= 2) {
                    int s = m >> 1, b = m & 1;      // row = s*B + b, B=2
                    int h = n >> 6, d = n & 63;     // col = h*64 + d
                    *(float4*)&C[(((size_t)b * H_ + h) * S_ + s) * DK_ + d] = r;
                } else {
                    r.x += bias[n + 0]; r.y += bias[n + 1];
                    r.z += bias[n + 2]; r.w += bias[n + 3];
                    *(float4*)&C[(size_t)m * D_ + n] = r;
                }
            }
        }
    }
}

// ---------------------------------------------------------------------------
// Scores: per (b,h), 64x64 tile of Q·K^T (scale already folded into Q),
// both masks applied, written to the attn region of d_out.
// ---------------------------------------------------------------------------
__global__ __launch_bounds__(256) void scores_kernel(
    const int* __restrict__ mask, const int* __restrict__ kpm,
    float* __restrict__ attn)
{
    constexpr int BT = 64;
    __shared__ float Qs[DK_][BT + 4];   // [d][q]
    __shared__ float Ks[DK_][BT + 4];   // [d][k]

    const int bh = blockIdx.z;
    const int b  = bh >> 4;             // H = 16
    const int q0 = blockIdx.y * BT;
    const int k0 = blockIdx.x * BT;
    const int tid = threadIdx.x;

    const float* Qb = g_Q + ((size_t)bh * S_ + q0) * DK_;
    const float* Kb = g_K + ((size_t)bh * S_ + k0) * DK_;

#pragma unroll
    for (int it = 0; it < 4; ++it) {
        int idx = tid + it * 256;       // over 1024 float4
        int row = idx >> 4;
        int c4  = (idx & 15) * 4;
        float4 v = *(const float4*)&Qb[(size_t)row * DK_ + c4];
        Qs[c4 + 0][row] = v.x; Qs[c4 + 1][row] = v.y;
        Qs[c4 + 2][row] = v.z; Qs[c4 + 3][row] = v.w;
        float4 w = *(const float4*)&Kb[(size_t)row * DK_ + c4];
        Ks[c4 + 0][row] = w.x; Ks[c4 + 1][row] = w.y;
        Ks[c4 + 2][row] = w.z; Ks[c4 + 3][row] = w.w;
    }
    __syncthreads();

    const int tx = tid & 15, ty = tid >> 4;
    float acc[4][4];
#pragma unroll
    for (int i = 0; i < 4; ++i)
#pragma unroll
        for (int j = 0; j < 4; ++j) acc[i][j] = 0.f;

#pragma unroll
    for (int d = 0; d < DK_; ++d) {
        float a[4], bb[4];
        *(float4*)a  = *(const float4*)&Qs[d][ty * 4];
        *(float4*)bb = *(const float4*)&Ks[d][tx * 4];
#pragma unroll
        for (int i = 0; i < 4; ++i)
#pragma unroll
            for (int j = 0; j < 4; ++j)
                acc[i][j] = fmaf(a[i], bb[j], acc[i][j]);
    }

#pragma unroll
    for (int i = 0; i < 4; ++i) {
        int q = q0 + ty * 4 + i;
        int k = k0 + tx * 4;
        int4 mm  = *(const int4*)&mask[(size_t)q * S_ + k];
        int4 kp  = *(const int4*)&kpm[(size_t)b * S_ + k];
        float4 r;
        r.x = (mm.x == 0 || kp.x == 0) ? -1.0e9f : acc[i][0];
        r.y = (mm.y == 0 || kp.y == 0) ? -1.0e9f : acc[i][1];
        r.z = (mm.z == 0 || kp.z == 0) ? -1.0e9f : acc[i][2];
        r.w = (mm.w == 0 || kp.w == 0) ? -1.0e9f : acc[i][3];
        *(float4*)&attn[((size_t)bh * S_ + q) * S_ + k] = r;
    }
}

// ---------------------------------------------------------------------------
// Row softmax, in place. One block per (b,h,q) row; 2048 floats = 8/thread.
// ---------------------------------------------------------------------------
__global__ __launch_bounds__(256) void softmax_kernel(float* __restrict__ attn)
{
    const size_t row = blockIdx.x;
    float* p = attn + row * (size_t)S_;
    const int tid = threadIdx.x;

    float v[8];
    *(float4*)&v[0] = *(const float4*)&p[tid * 8];
    *(float4*)&v[4] = *(const float4*)&p[tid * 8 + 4];

    float mx = v[0];
#pragma unroll
    for (int i = 1; i < 8; ++i) mx = fmaxf(mx, v[i]);
#pragma unroll
    for (int o = 16; o; o >>= 1) mx = fmaxf(mx, __shfl_xor_sync(0xffffffffu, mx, o));

    __shared__ float sred[8];
    const int warp = tid >> 5, lane = tid & 31;
    if (lane == 0) sred[warp] = mx;
    __syncthreads();
    if (tid == 0) {
        float m = sred[0];
#pragma unroll
        for (int i = 1; i < 8; ++i) m = fmaxf(m, sred[i]);
        sred[0] = m;
    }
    __syncthreads();
    mx = sred[0];

    float sum = 0.f;
#pragma unroll
    for (int i = 0; i < 8; ++i) { v[i] = __expf(v[i] - mx); sum += v[i]; }
#pragma unroll
    for (int o = 16; o; o >>= 1) sum += __shfl_xor_sync(0xffffffffu, sum, o);
    __syncthreads();               // everyone done reading sred[0]
    if (lane == 0) sred[warp] = sum;
    __syncthreads();
    if (tid == 0) {
        float s = 0.f;
#pragma unroll
        for (int i = 0; i < 8; ++i) s += sred[i];
        sred[0] = s;
    }
    __syncthreads();
    const float inv = 1.0f / sred[0];

#pragma unroll
    for (int i = 0; i < 8; ++i) v[i] *= inv;
    *(float4*)&p[tid * 8]     = *(float4*)&v[0];
    *(float4*)&p[tid * 8 + 4] = *(float4*)&v[4];
}

// ---------------------------------------------------------------------------
// A·V: per (b,h), ctx[q, b, h*64+d] = sum_k attn[q,k] * V[k,d]
// ---------------------------------------------------------------------------
__global__ __launch_bounds__(256) void av_kernel(const float* __restrict__ attn)
{
    constexpr int BM = 64, BK = 32;     // BN = DK_ = 64
    __shared__ float At[BK][BM + 4];    // [k][q]
    __shared__ float Vs[BK][DK_ + 4];   // [k][d]

    const int bh = blockIdx.y;
    const int b = bh >> 4, h = bh & 15;
    const int q0 = blockIdx.x * BM;
    const int tid = threadIdx.x;
    const int tx = tid & 15, ty = tid >> 4;

    const float* Ab = attn + ((size_t)bh * S_ + q0) * S_;
    const float* Vb = g_V + (size_t)bh * S_ * DK_;

    float acc[4][4];
#pragma unroll
    for (int i = 0; i < 4; ++i)
#pragma unroll
        for (int j = 0; j < 4; ++j) acc[i][j] = 0.f;

    for (int k0 = 0; k0 < S_; k0 += BK) {
#pragma unroll
        for (int it = 0; it < 2; ++it) {
            int idx = tid + it * 256;   // over 512 float4 (64x32 A tile)
            int row = idx >> 3;
            int c4  = (idx & 7) * 4;
            float4 v = *(const float4*)&Ab[(size_t)row * S_ + k0 + c4];
            At[c4 + 0][row] = v.x; At[c4 + 1][row] = v.y;
            At[c4 + 2][row] = v.z; At[c4 + 3][row] = v.w;
        }
#pragma unroll
        for (int it = 0; it < 2; ++it) {
            int idx = tid + it * 256;   // over 512 float4 (32x64 V tile)
            int row = idx >> 4;
            int c4  = (idx & 15) * 4;
            *(float4*)&Vs[row][c4] =
                *(const float4*)&Vb[(size_t)(k0 + row) * DK_ + c4];
        }
        __syncthreads();
#pragma unroll
        for (int k = 0; k < BK; ++k) {
            float a[4], vv[4];
            *(float4*)a  = *(const float4*)&At[k][ty * 4];
            *(float4*)vv = *(const float4*)&Vs[k][tx * 4];
#pragma unroll
            for (int i = 0; i < 4; ++i)
#pragma unroll
                for (int j = 0; j < 4; ++j)
                    acc[i][j] = fmaf(a[i], vv[j], acc[i][j]);
        }
        __syncthreads();
    }

#pragma unroll
    for (int i = 0; i < 4; ++i) {
        int q = q0 + ty * 4 + i;
        float4 r = make_float4(acc[i][0], acc[i][1], acc[i][2], acc[i][3]);
        *(float4*)&g_ctx[((size_t)q * B_ + b) * D_ + h * DK_ + tx * 4] = r;
    }
}

// ---------------------------------------------------------------------------
extern "C" void kernel_launch(void* const* d_in, const int* in_sizes, int n_in,
                              void* d_out, int out_size)
{
    (void)in_sizes; (void)n_in; (void)out_size;
    const float* query = (const float*)d_in[0];
    const float* key   = (const float*)d_in[1];
    const float* value = (const float*)d_in[2];
    const int*   mask  = (const int*)d_in[3];
    const int*   kpm   = (const int*)d_in[4];
    const float* Wq    = (const float*)d_in[5];
    const float* Wk    = (const float*)d_in[6];
    const float* Wv    = (const float*)d_in[7];
    const float* Wo    = (const float*)d_in[8];
    const float* bo    = (const float*)d_in[9];

    float* out  = (float*)d_out;
    float* attn = out + (size_t)S_ * B_ * D_;   // tuple: (out, attn)

    dim3 ggrid(D_ / 128, R_ / 128);             // (8, 32)
    gemm_nt_kernel<<<ggrid, 256>>>(query, Wq, nullptr, nullptr, 0.125f, 0);
    gemm_nt_kernel<<<ggrid, 256>>>(key,   Wk, nullptr, nullptr, 1.0f,   1);
    gemm_nt_kernel<<<ggrid, 256>>>(value, Wv, nullptr, nullptr, 1.0f,   2);

    scores_kernel<<<dim3(S_ / 64, S_ / 64, B_ * H_), 256>>>(mask, kpm, attn);
    softmax_kernel<<<B_ * H_ * S_, 256>>>(attn);
    av_kernel<<<dim3(S_ / 64, B_ * H_), 256>>>(attn);

    gemm_nt_kernel<<<ggrid, 256>>>(nullptr, Wo, out, bo, 1.0f, 3);
}

// round 3
// speedup vs baseline: 1.0686x; 1.0686x over previous
#include <cuda_runtime.h>
#include <cstdint>

static constexpr int S_  = 2048;
static constexpr int B_  = 2;
static constexpr int D_  = 1024;
static constexpr int H_  = 16;
static constexpr int DK_ = 64;
static constexpr int R_  = S_ * B_;   // 4096 token rows

// Scratch (device globals; no allocation allowed)
__device__ float g_Q[(size_t)B_ * H_ * S_ * DK_];   // (B,H,S,dk)
__device__ float g_K[(size_t)B_ * H_ * S_ * DK_];
__device__ float g_V[(size_t)B_ * H_ * S_ * DK_];
__device__ float g_ctx[(size_t)R_ * D_];            // (S,B,D)

// ---------------------------------------------------------------------------
// 3xTF32 helpers
// ---------------------------------------------------------------------------
__device__ __forceinline__ void split_tf32(float x, uint32_t& hi, uint32_t& lo)
{
    asm("cvt.rna.tf32.f32 %0, %1;" : "=r"(hi) : "f"(x));
    float lf = x - __uint_as_float(hi);
    asm("cvt.rna.tf32.f32 %0, %1;" : "=r"(lo) : "f"(lf));
}

__device__ __forceinline__ void mma_tf32(float* c, const uint32_t* a, const uint32_t* b)
{
    asm volatile(
        "mma.sync.aligned.m16n8k8.row.col.f32.tf32.tf32.f32 "
        "{%0,%1,%2,%3}, {%4,%5,%6,%7}, {%8,%9}, {%0,%1,%2,%3};"
        : "+f"(c[0]), "+f"(c[1]), "+f"(c[2]), "+f"(c[3])
        : "r"(a[0]), "r"(a[1]), "r"(a[2]), "r"(a[3]), "r"(b[0]), "r"(b[1]));
}

// ---------------------------------------------------------------------------
// Unified NT GEMM on tensor cores: C[M,N] = X[M,K] @ W[N,K]^T
//  mode 0/1/2: X=q/k/v input, W=Wq/Wk/Wv -> scatter into g_Q/g_K/g_V, *scale
//  mode 3    : X=g_ctx, W=Wo -> Cout row-major + bias
//  mode 4    : batched scores: X=g_Q+z*S*dk, W=g_K+z*S*dk, K=64,
//              masks applied, -> attn (Cout) at z*S*S
// Block: 256 thr, tile 128x128, BK=32. Warps 2(m) x 4(n), warp tile 64x32.
// ---------------------------------------------------------------------------
__global__ __launch_bounds__(256) void gemm_tc(
    const float* __restrict__ X, const float* __restrict__ W,
    const int* __restrict__ mask, const int* __restrict__ kpm,
    float* __restrict__ Cout, const float* __restrict__ bias,
    float scale, int K, int mode)
{
    __shared__ float sA[128 * 32];
    __shared__ float sB[128 * 32];

    const int tid  = threadIdx.x;
    const int lane = tid & 31;
    const int w    = tid >> 5;
    const int wm   = w >> 2;        // 0..1
    const int wn   = w & 3;         // 0..3
    const int m0   = blockIdx.y * 128;
    const int n0   = blockIdx.x * 128;

    const float* Xp;
    const float* Wp;
    if (mode == 4) {
        size_t off = (size_t)blockIdx.z * S_ * DK_;
        Xp = g_Q + off;
        Wp = g_K + off;
    } else {
        Xp = (mode == 3) ? (const float*)g_ctx : X;
        Wp = W;
    }

    float c[16][4];
#pragma unroll
    for (int i = 0; i < 16; ++i)
#pragma unroll
        for (int j = 0; j < 4; ++j) c[i][j] = 0.f;

    const int lr  = lane >> 2;      // 0..7
    const int lk  = lane & 3;       // 0..3

    for (int k0 = 0; k0 < K; k0 += 32) {
        // --- load A tile 128x32 (swizzled rows) ---
#pragma unroll
        for (int i = 0; i < 4; ++i) {
            int idx = tid + i * 256;
            int row = idx >> 3;
            int c4  = (idx & 7) << 2;
            float4 v = *(const float4*)&Xp[(size_t)(m0 + row) * K + k0 + c4];
            *(float4*)&sA[row * 32 + (c4 ^ ((row & 7) * 4))] = v;
        }
        // --- load B tile 128x32 from W rows (swizzled) ---
#pragma unroll
        for (int i = 0; i < 4; ++i) {
            int idx = tid + i * 256;
            int row = idx >> 3;
            int c4  = (idx & 7) << 2;
            float4 v = *(const float4*)&Wp[(size_t)(n0 + row) * K + k0 + c4];
            *(float4*)&sB[row * 32 + (c4 ^ ((row & 7) * 4))] = v;
        }
        __syncthreads();

#pragma unroll
        for (int kk = 0; kk < 4; ++kk) {
            const int kb = kk * 8;

            uint32_t ahi[4][4], alo[4][4];
#pragma unroll
            for (int mt = 0; mt < 4; ++mt) {
                int rbase = wm * 64 + mt * 16 + lr;
#pragma unroll
                for (int j = 0; j < 4; ++j) {
                    int r    = rbase + ((j & 1) << 3);
                    int kcol = kb + lk + ((j >> 1) << 2);
                    float x  = sA[r * 32 + (kcol ^ ((r & 7) * 4))];
                    split_tf32(x, ahi[mt][j], alo[mt][j]);
                }
            }
            uint32_t bhi[4][2], blo[4][2];
#pragma unroll
            for (int nt = 0; nt < 4; ++nt) {
                int nb = wn * 32 + nt * 8 + lr;
#pragma unroll
                for (int j = 0; j < 2; ++j) {
                    int kcol = kb + lk + (j << 2);
                    float x  = sB[nb * 32 + (kcol ^ ((nb & 7) * 4))];
                    split_tf32(x, bhi[nt][j], blo[nt][j]);
                }
            }
#pragma unroll
            for (int mt = 0; mt < 4; ++mt)
#pragma unroll
                for (int nt = 0; nt < 4; ++nt) {
                    float* cc = c[mt * 4 + nt];
                    mma_tf32(cc, ahi[mt], bhi[nt]);
                    mma_tf32(cc, ahi[mt], blo[nt]);
                    mma_tf32(cc, alo[mt], bhi[nt]);
                }
        }
        __syncthreads();
    }

    // --- epilogue ---
    const int lc2 = (lane & 3) * 2;
    if (mode <= 2) {
        float* C = (mode == 0) ? g_Q : (mode == 1) ? g_K : g_V;
#pragma unroll
        for (int mt = 0; mt < 4; ++mt)
#pragma unroll
            for (int nt = 0; nt < 4; ++nt) {
                int col = n0 + wn * 32 + nt * 8 + lc2;
                int h = col >> 6, d = col & 63;
#pragma unroll
                for (int half = 0; half < 2; ++half) {
                    int r = m0 + wm * 64 + mt * 16 + lr + half * 8;
                    int s = r >> 1, bb = r & 1;
                    float2 v;
                    v.x = c[mt * 4 + nt][half * 2 + 0] * scale;
                    v.y = c[mt * 4 + nt][half * 2 + 1] * scale;
                    *(float2*)&C[(((size_t)bb * H_ + h) * S_ + s) * DK_ + d] = v;
                }
            }
    } else if (mode == 3) {
#pragma unroll
        for (int mt = 0; mt < 4; ++mt)
#pragma unroll
            for (int nt = 0; nt < 4; ++nt) {
                int col = n0 + wn * 32 + nt * 8 + lc2;
                float b0 = bias[col], b1 = bias[col + 1];
#pragma unroll
                for (int half = 0; half < 2; ++half) {
                    int r = m0 + wm * 64 + mt * 16 + lr + half * 8;
                    float2 v;
                    v.x = c[mt * 4 + nt][half * 2 + 0] + b0;
                    v.y = c[mt * 4 + nt][half * 2 + 1] + b1;
                    *(float2*)&Cout[(size_t)r * D_ + col] = v;
                }
            }
    } else {  // mode 4: scores with masks
        const int z  = blockIdx.z;
        const int bb = z >> 4;
        float* attn  = Cout + (size_t)z * S_ * S_;
#pragma unroll
        for (int mt = 0; mt < 4; ++mt)
#pragma unroll
            for (int nt = 0; nt < 4; ++nt) {
                int col = n0 + wn * 32 + nt * 8 + lc2;
                int kp0 = kpm[(size_t)bb * S_ + col];
                int kp1 = kpm[(size_t)bb * S_ + col + 1];
#pragma unroll
                for (int half = 0; half < 2; ++half) {
                    int r = m0 + wm * 64 + mt * 16 + lr + half * 8;
                    const int* mrow = mask + (size_t)r * S_;
                    float2 v;
                    v.x = (mrow[col] == 0 || kp0 == 0) ? -1.0e9f
                          : c[mt * 4 + nt][half * 2 + 0];
                    v.y = (mrow[col + 1] == 0 || kp1 == 0) ? -1.0e9f
                          : c[mt * 4 + nt][half * 2 + 1];
                    *(float2*)&attn[(size_t)r * S_ + col] = v;
                }
            }
    }
}

// ---------------------------------------------------------------------------
// Row softmax, in place. One block per (b,h,q) row.
// ---------------------------------------------------------------------------
__global__ __launch_bounds__(256) void softmax_kernel(float* __restrict__ attn)
{
    const size_t row = blockIdx.x;
    float* p = attn + row * (size_t)S_;
    const int tid = threadIdx.x;

    float v[8];
    *(float4*)&v[0] = *(const float4*)&p[tid * 8];
    *(float4*)&v[4] = *(const float4*)&p[tid * 8 + 4];

    float mx = v[0];
#pragma unroll
    for (int i = 1; i < 8; ++i) mx = fmaxf(mx, v[i]);
#pragma unroll
    for (int o = 16; o; o >>= 1) mx = fmaxf(mx, __shfl_xor_sync(0xffffffffu, mx, o));

    __shared__ float sred[8];
    const int warp = tid >> 5, lane = tid & 31;
    if (lane == 0) sred[warp] = mx;
    __syncthreads();
    if (tid == 0) {
        float m = sred[0];
#pragma unroll
        for (int i = 1; i < 8; ++i) m = fmaxf(m, sred[i]);
        sred[0] = m;
    }
    __syncthreads();
    mx = sred[0];

    float sum = 0.f;
#pragma unroll
    for (int i = 0; i < 8; ++i) { v[i] = __expf(v[i] - mx); sum += v[i]; }
#pragma unroll
    for (int o = 16; o; o >>= 1) sum += __shfl_xor_sync(0xffffffffu, sum, o);
    __syncthreads();
    if (lane == 0) sred[warp] = sum;
    __syncthreads();
    if (tid == 0) {
        float s = 0.f;
#pragma unroll
        for (int i = 0; i < 8; ++i) s += sred[i];
        sred[0] = s;
    }
    __syncthreads();
    const float inv = 1.0f / sred[0];

#pragma unroll
    for (int i = 0; i < 8; ++i) v[i] *= inv;
    *(float4*)&p[tid * 8]     = *(float4*)&v[0];
    *(float4*)&p[tid * 8 + 4] = *(float4*)&v[4];
}

// ---------------------------------------------------------------------------
// A.V on tensor cores: per z=(b,h), ctx = attn[z] (2048x2048) @ V[z] (2048x64)
// Block: 256 thr, tile 128(m) x 64(n), BK=32. Warps 4(m) x 2(n), warp 32x32.
// ---------------------------------------------------------------------------
__global__ __launch_bounds__(256) void av_tc(const float* __restrict__ attn_g)
{
    __shared__ float sA[128 * 32];
    __shared__ float sV[32 * 72];

    const int tid  = threadIdx.x;
    const int lane = tid & 31;
    const int w    = tid >> 5;
    const int wm   = w >> 1;        // 0..3
    const int wn   = w & 1;         // 0..1
    const int m0   = blockIdx.x * 128;
    const int z    = blockIdx.z;

    const float* Ab = attn_g + (size_t)z * S_ * S_;
    const float* Vb = g_V + (size_t)z * S_ * DK_;

    float c[8][4];
#pragma unroll
    for (int i = 0; i < 8; ++i)
#pragma unroll
        for (int j = 0; j < 4; ++j) c[i][j] = 0.f;

    const int lr = lane >> 2, lk = lane & 3;

    for (int k0 = 0; k0 < S_; k0 += 32) {
#pragma unroll
        for (int i = 0; i < 4; ++i) {
            int idx = tid + i * 256;
            int row = idx >> 3;
            int c4  = (idx & 7) << 2;
            float4 v = *(const float4*)&Ab[(size_t)(m0 + row) * S_ + k0 + c4];
            *(float4*)&sA[row * 32 + (c4 ^ ((row & 7) * 4))] = v;
        }
#pragma unroll
        for (int i = 0; i < 2; ++i) {
            int idx = tid + i * 256;
            int row = idx >> 4;             // k row 0..31
            int c4  = (idx & 15) << 2;      // n 0..60
            float4 v = *(const float4*)&Vb[(size_t)(k0 + row) * DK_ + c4];
            *(float4*)&sV[row * 72 + c4] = v;
        }
        __syncthreads();

#pragma unroll
        for (int kk = 0; kk < 4; ++kk) {
            const int kb = kk * 8;
            uint32_t ahi[2][4], alo[2][4];
#pragma unroll
            for (int mt = 0; mt < 2; ++mt) {
                int rbase = wm * 32 + mt * 16 + lr;
#pragma unroll
                for (int j = 0; j < 4; ++j) {
                    int r    = rbase + ((j & 1) << 3);
                    int kcol = kb + lk + ((j >> 1) << 2);
                    float x  = sA[r * 32 + (kcol ^ ((r & 7) * 4))];
                    split_tf32(x, ahi[mt][j], alo[mt][j]);
                }
            }
            uint32_t bhi[4][2], blo[4][2];
#pragma unroll
            for (int nt = 0; nt < 4; ++nt) {
                int nb = wn * 32 + nt * 8 + lr;
#pragma unroll
                for (int j = 0; j < 2; ++j) {
                    int krow = kb + lk + (j << 2);
                    float x  = sV[krow * 72 + nb];
                    split_tf32(x, bhi[nt][j], blo[nt][j]);
                }
            }
#pragma unroll
            for (int mt = 0; mt < 2; ++mt)
#pragma unroll
                for (int nt = 0; nt < 4; ++nt) {
                    float* cc = c[mt * 4 + nt];
                    mma_tf32(cc, ahi[mt], bhi[nt]);
                    mma_tf32(cc, ahi[mt], blo[nt]);
                    mma_tf32(cc, alo[mt], bhi[nt]);
                }
        }
        __syncthreads();
    }

    const int bb = z >> 4, h = z & 15;
    const int lc2 = (lane & 3) * 2;
#pragma unroll
    for (int mt = 0; mt < 2; ++mt)
#pragma unroll
        for (int nt = 0; nt < 4; ++nt) {
            int col = wn * 32 + nt * 8 + lc2;    // d within 0..63
#pragma unroll
            for (int half = 0; half < 2; ++half) {
                int r = m0 + wm * 32 + mt * 16 + lr + half * 8;   // q
                float2 v;
                v.x = c[mt * 4 + nt][half * 2 + 0];
                v.y = c[mt * 4 + nt][half * 2 + 1];
                *(float2*)&g_ctx[((size_t)r * B_ + bb) * D_ + h * DK_ + col] = v;
            }
        }
}

// ---------------------------------------------------------------------------
extern "C" void kernel_launch(void* const* d_in, const int* in_sizes, int n_in,
                              void* d_out, int out_size)
{
    (void)in_sizes; (void)n_in; (void)out_size;
    const float* query = (const float*)d_in[0];
    const float* key   = (const float*)d_in[1];
    const float* value = (const float*)d_in[2];
    const int*   mask  = (const int*)d_in[3];
    const int*   kpm   = (const int*)d_in[4];
    const float* Wq    = (const float*)d_in[5];
    const float* Wk    = (const float*)d_in[6];
    const float* Wv    = (const float*)d_in[7];
    const float* Wo    = (const float*)d_in[8];
    const float* bo    = (const float*)d_in[9];

    float* out  = (float*)d_out;
    float* attn = out + (size_t)S_ * B_ * D_;   // tuple: (out, attn)

    dim3 pgrid(D_ / 128, R_ / 128);             // (8, 32)
    gemm_tc<<<pgrid, 256>>>(query, Wq, nullptr, nullptr, nullptr, nullptr, 0.125f, D_, 0);
    gemm_tc<<<pgrid, 256>>>(key,   Wk, nullptr, nullptr, nullptr, nullptr, 1.0f,   D_, 1);
    gemm_tc<<<pgrid, 256>>>(value, Wv, nullptr, nullptr, nullptr, nullptr, 1.0f,   D_, 2);

    gemm_tc<<<dim3(S_ / 128, S_ / 128, B_ * H_), 256>>>(
        nullptr, nullptr, mask, kpm, attn, nullptr, 1.0f, DK_, 4);

    softmax_kernel<<<B_ * H_ * S_, 256>>>(attn);

    av_tc<<<dim3(S_ / 128, 1, B_ * H_), 256>>>(attn);

    gemm_tc<<<pgrid, 256>>>(nullptr, Wo, nullptr, nullptr, out, bo, 1.0f, D_, 3);
}

// round 8
// speedup vs baseline: 1.5881x; 1.4862x over previous
#include <cuda_runtime.h>
#include <cuda_bf16.h>
#include <cstdint>

static constexpr int S_  = 2048;
static constexpr int B_  = 2;
static constexpr int D_  = 1024;
static constexpr int H_  = 16;
static constexpr int DK_ = 64;
static constexpr int R_  = S_ * B_;     // 4096 token rows
static constexpr int Z_  = B_ * H_;     // 32 (b,h) planes

// ---------------------------------------------------------------------------
// Device-global scratch (no allocations allowed)
// ---------------------------------------------------------------------------
__device__ __nv_bfloat16 g_Xhi[(size_t)R_ * D_];
__device__ __nv_bfloat16 g_Xlo[(size_t)R_ * D_];
__device__ __nv_bfloat16 g_Whi[(size_t)D_ * D_];
__device__ __nv_bfloat16 g_Wlo[(size_t)D_ * D_];
__device__ __nv_bfloat16 g_Qhi[(size_t)Z_ * S_ * DK_];
__device__ __nv_bfloat16 g_Qlo[(size_t)Z_ * S_ * DK_];
__device__ __nv_bfloat16 g_Khi[(size_t)Z_ * S_ * DK_];
__device__ __nv_bfloat16 g_Klo[(size_t)Z_ * S_ * DK_];
__device__ __nv_bfloat16 g_Vthi[(size_t)Z_ * DK_ * S_];   // (z, d, s)
__device__ __nv_bfloat16 g_Vtlo[(size_t)Z_ * DK_ * S_];
__device__ unsigned char g_cmb[(size_t)B_ * S_ * S_];     // 1 = masked

// ---------------------------------------------------------------------------
// helpers
// ---------------------------------------------------------------------------
__device__ __forceinline__ uint32_t s2u(const void* p) {
    uint32_t a;
    asm("{ .reg .u64 t; cvta.to.shared.u64 t, %1; cvt.u32.u64 %0, t; }"
        : "=r"(a) : "l"(p));
    return a;
}
__device__ __forceinline__ void cp16(uint32_t d, const void* s) {
    asm volatile(
        "{ .reg .u64 g; cvta.to.global.u64 g, %1; "
        "cp.async.cg.shared.global [%0], [g], 16; }"
        :: "r"(d), "l"(s));
}
__device__ __forceinline__ void cp_commit() {
    asm volatile("cp.async.commit_group;" ::: "memory");
}
__device__ __forceinline__ void cp_wait0() {
    asm volatile("cp.async.wait_group 0;" ::: "memory");
}
__device__ __forceinline__ void cp_wait1() {
    asm volatile("cp.async.wait_group 1;" ::: "memory");
}

__device__ __forceinline__ void mma_bf16(float* c, const uint32_t* a, const uint32_t* b)
{
    asm volatile(
        "mma.sync.aligned.m16n8k16.row.col.f32.bf16.bf16.f32 "
        "{%0,%1,%2,%3}, {%4,%5,%6,%7}, {%8,%9}, {%0,%1,%2,%3};"
        : "+f"(c[0]), "+f"(c[1]), "+f"(c[2]), "+f"(c[3])
        : "r"(a[0]), "r"(a[1]), "r"(a[2]), "r"(a[3]), "r"(b[0]), "r"(b[1]));
}

__device__ __forceinline__ void bsplit(float v, __nv_bfloat16& h, __nv_bfloat16& l) {
    h = __float2bfloat16(v);
    l = __float2bfloat16(v - __bfloat162float(h));
}
__device__ __forceinline__ __nv_bfloat162 bf2(__nv_bfloat16 a, __nv_bfloat16 b) {
    __nv_bfloat162 t; t.x = a; t.y = b; return t;
}
__device__ __forceinline__ uint32_t pack2(__nv_bfloat16 a, __nv_bfloat16 b) {
    return (uint32_t)__bfloat16_as_ushort(a) |
           ((uint32_t)__bfloat16_as_ushort(b) << 16);
}

// ---------------------------------------------------------------------------
// fp32 -> bf16 hi/lo split.  sel 0: g_X*, sel 1: g_W*
// ---------------------------------------------------------------------------
__global__ __launch_bounds__(256) void conv_split(const float* __restrict__ src,
                                                  int sel, int n4)
{
    __nv_bfloat16* hi = sel ? g_Whi : g_Xhi;
    __nv_bfloat16* lo = sel ? g_Wlo : g_Xlo;
    int i = blockIdx.x * 256 + threadIdx.x;
    if (i >= n4) return;
    float4 v = ((const float4*)src)[i];
    __nv_bfloat16 h0, h1, h2, h3, l0, l1, l2, l3;
    bsplit(v.x, h0, l0); bsplit(v.y, h1, l1);
    bsplit(v.z, h2, l2); bsplit(v.w, h3, l3);
    ((__nv_bfloat162*)hi)[i * 2]     = bf2(h0, h1);
    ((__nv_bfloat162*)hi)[i * 2 + 1] = bf2(h2, h3);
    ((__nv_bfloat162*)lo)[i * 2]     = bf2(l0, l1);
    ((__nv_bfloat162*)lo)[i * 2 + 1] = bf2(l2, l3);
}

// combined mask flags: cmb[b][q][k] = (mask==0 || kpm==0)
__global__ __launch_bounds__(256) void mask_cmb(const int* __restrict__ mask,
                                                const int* __restrict__ kpm)
{
    int b = blockIdx.y;
    size_t i = (size_t)blockIdx.x * 256 + threadIdx.x;   // per uchar4
    int q  = (int)(i >> 9);
    int k4 = (int)(i & 511) << 2;
    int4 m  = *(const int4*)&mask[(size_t)q * S_ + k4];
    int4 kp = *(const int4*)&kpm[(size_t)b * S_ + k4];
    uchar4 r;
    r.x = (m.x == 0 || kp.x == 0); r.y = (m.y == 0 || kp.y == 0);
    r.z = (m.z == 0 || kp.z == 0); r.w = (m.w == 0 || kp.w == 0);
    *(uchar4*)&g_cmb[((size_t)b * S_ + q) * S_ + k4] = r;
}

// ---------------------------------------------------------------------------
// proj_mma: C[4096,1024] = X @ W^T, tile 128x128, BK=32, warps 2(m)x4(n).
//  mode 0: -> g_Qhi/lo (scale 1/8)   mode 1: -> g_Khi/lo
//  mode 2: -> g_Vthi/lo (transposed) mode 3: -> outp (fp32 + bias)
// smem: 2 buffers x 4 arrays (Xhi,Xlo,Whi,Wlo) of 128 rows x 40 halves (80B).
// ---------------------------------------------------------------------------
static constexpr int PROJ_SMEM = 2 * 4 * 128 * 80;   // 81920

__global__ __launch_bounds__(256) void proj_mma(const float* __restrict__ bias,
                                                float* __restrict__ outp,
                                                float scale, int mode)
{
    extern __shared__ __align__(16) char sm[];
    uint32_t sb = s2u(sm);
    const int tid = threadIdx.x, lane = tid & 31, w = tid >> 5;
    const int wm = w >> 2, wn = w & 3;
    const int m0 = blockIdx.y * 128, n0 = blockIdx.x * 128;
    const int lr = lane >> 2, lk = lane & 3, lc2 = (lane & 3) * 2;

    const __nv_bfloat16* srcs[4] = { g_Xhi, g_Xlo, g_Whi, g_Wlo };

    float acc[16][4];
#pragma unroll
    for (int i = 0; i < 16; ++i)
#pragma unroll
        for (int j = 0; j < 4; ++j) acc[i][j] = 0.f;

    auto prefetch = [&](int c) {
        int k0 = c * 32;
        uint32_t bufb = sb + (uint32_t)(c & 1) * 40960;
#pragma unroll
        for (int i = 0; i < 8; ++i) {
            int g = tid + i * 256;
            int t = g >> 9, idx = g & 511;
            int row = idx >> 2, gc = idx & 3;
            int grow = ((t < 2) ? m0 : n0) + row;
            uint32_t dst = bufb + (uint32_t)t * 10240 + row * 80 + gc * 16;
            cp16(dst, srcs[t] + (size_t)grow * D_ + k0 + gc * 8);
        }
        cp_commit();
    };

    prefetch(0);
    for (int c = 0; c < 32; ++c) {
        if (c + 1 < 32) { prefetch(c + 1); cp_wait1(); }
        else            { cp_wait0(); }
        __syncthreads();
        const uint32_t* XH = (const uint32_t*)(sm + (c & 1) * 40960);
        const uint32_t* XL = XH + 2560;
        const uint32_t* WH = XH + 5120;
        const uint32_t* WL = XH + 7680;
#pragma unroll
        for (int s = 0; s < 2; ++s) {
            uint32_t ah[4][4], al[4][4], bh[4][2], bl[4][2];
#pragma unroll
            for (int mt = 0; mt < 4; ++mt) {
                int r = wm * 64 + mt * 16 + lr;
                int w0 = r * 20 + s * 8 + lk, w1 = (r + 8) * 20 + s * 8 + lk;
                ah[mt][0] = XH[w0]; ah[mt][1] = XH[w1];
                ah[mt][2] = XH[w0 + 4]; ah[mt][3] = XH[w1 + 4];
                al[mt][0] = XL[w0]; al[mt][1] = XL[w1];
                al[mt][2] = XL[w0 + 4]; al[mt][3] = XL[w1 + 4];
            }
#pragma unroll
            for (int nt = 0; nt < 4; ++nt) {
                int cc = wn * 32 + nt * 8 + lr;
                int wv = cc * 20 + s * 8 + lk;
                bh[nt][0] = WH[wv]; bh[nt][1] = WH[wv + 4];
                bl[nt][0] = WL[wv]; bl[nt][1] = WL[wv + 4];
            }
#pragma unroll
            for (int mt = 0; mt < 4; ++mt)
#pragma unroll
                for (int nt = 0; nt < 4; ++nt) {
                    float* cc = acc[mt * 4 + nt];
                    mma_bf16(cc, ah[mt], bh[nt]);
                    mma_bf16(cc, ah[mt], bl[nt]);
                    mma_bf16(cc, al[mt], bh[nt]);
                }
        }
        __syncthreads();
    }

    // ---- epilogue ----
    if (mode <= 1) {
        __nv_bfloat16* Chi = mode ? g_Khi : g_Qhi;
        __nv_bfloat16* Clo = mode ? g_Klo : g_Qlo;
#pragma unroll
        for (int mt = 0; mt < 4; ++mt)
#pragma unroll
            for (int nt = 0; nt < 4; ++nt) {
                int col = n0 + wn * 32 + nt * 8 + lc2;
                int h = col >> 6, d = col & 63;
                const float* a = acc[mt * 4 + nt];
#pragma unroll
                for (int hf = 0; hf < 2; ++hf) {
                    int r = m0 + wm * 64 + mt * 16 + lr + hf * 8;
                    int ss = r >> 1, bb = r & 1;
                    float v0 = a[hf * 2 + 0] * scale;
                    float v1 = a[hf * 2 + 1] * scale;
                    __nv_bfloat16 h0, h1, l0, l1;
                    bsplit(v0, h0, l0); bsplit(v1, h1, l1);
                    size_t o = (((size_t)(bb * H_ + h)) * S_ + ss) * DK_ + d;
                    *(__nv_bfloat162*)&Chi[o] = bf2(h0, h1);
                    *(__nv_bfloat162*)&Clo[o] = bf2(l0, l1);
                }
            }
    } else if (mode == 3) {
#pragma unroll
        for (int mt = 0; mt < 4; ++mt)
#pragma unroll
            for (int nt = 0; nt < 4; ++nt) {
                int col = n0 + wn * 32 + nt * 8 + lc2;
                float b0 = bias[col], b1 = bias[col + 1];
                const float* a = acc[mt * 4 + nt];
#pragma unroll
                for (int hf = 0; hf < 2; ++hf) {
                    int r = m0 + wm * 64 + mt * 16 + lr + hf * 8;
                    float2 v;
                    v.x = a[hf * 2 + 0] + b0;
                    v.y = a[hf * 2 + 1] + b1;
                    *(float2*)&outp[(size_t)r * D_ + col] = v;
                }
            }
    } else {  // mode 2: V -> transposed g_Vt (stage fp32 in smem, scatter)
        float* sD = (float*)sm;   // 128 x 132
#pragma unroll
        for (int mt = 0; mt < 4; ++mt)
#pragma unroll
            for (int nt = 0; nt < 4; ++nt) {
                int col = wn * 32 + nt * 8 + lc2;
                const float* a = acc[mt * 4 + nt];
#pragma unroll
                for (int hf = 0; hf < 2; ++hf) {
                    int r = wm * 64 + mt * 16 + lr + hf * 8;
                    float2 v = make_float2(a[hf * 2 + 0], a[hf * 2 + 1]);
                    *(float2*)&sD[r * 132 + col] = v;
                }
            }
        __syncthreads();
        for (int e = tid; e < 16384; e += 256) {
            int row = e & 127, col = e >> 7;
            float v = sD[row * 132 + col];
            int tok = m0 + row;
            int ss = tok >> 1, bb = tok & 1;
            int gc = n0 + col;
            int h = gc >> 6, d = gc & 63;
            __nv_bfloat16 hh, ll;
            bsplit(v, hh, ll);
            size_t o = ((size_t)(bb * H_ + h) * DK_ + d) * S_ + ss;
            g_Vthi[o] = hh;
            g_Vtlo[o] = ll;
        }
    }
}

// ---------------------------------------------------------------------------
// scores_mma: per z, 128(q) x 128(k) tile of Q.K^T (K=64), masks, -> attn.
// smem arrays QH,QL,KH,KL: 128 rows x 72 halves (144B) = 18432B each.
// ---------------------------------------------------------------------------
static constexpr int SC_SMEM = 4 * 128 * 144;        // 73728

__global__ __launch_bounds__(256) void scores_mma(float* __restrict__ attn_g)
{
    extern __shared__ __align__(16) char sm[];
    uint32_t sb = s2u(sm);
    const int tid = threadIdx.x, lane = tid & 31, w = tid >> 5;
    const int wm = w >> 2, wn = w & 3;
    const int n0 = blockIdx.x * 128, m0 = blockIdx.y * 128, z = blockIdx.z;
    const int b = z >> 4;
    const int lr = lane >> 2, lk = lane & 3, lc2 = (lane & 3) * 2;

    const size_t zoff = (size_t)z * S_ * DK_;
    const __nv_bfloat16* srcs[4] = { g_Qhi + zoff, g_Qlo + zoff,
                                     g_Khi + zoff, g_Klo + zoff };
#pragma unroll
    for (int i = 0; i < 16; ++i) {
        int g = tid + i * 256;
        int t = g >> 10, idx = g & 1023;
        int row = idx >> 3, gc = idx & 7;
        int grow = ((t < 2) ? m0 : n0) + row;
        uint32_t dst = sb + (uint32_t)t * 18432 + row * 144 + gc * 16;
        cp16(dst, srcs[t] + (size_t)grow * DK_ + gc * 8);
    }
    cp_commit();
    cp_wait0();
    __syncthreads();

    float acc[16][4];
#pragma unroll
    for (int i = 0; i < 16; ++i)
#pragma unroll
        for (int j = 0; j < 4; ++j) acc[i][j] = 0.f;

    const uint32_t* QH = (const uint32_t*)sm;
    const uint32_t* QL = QH + 4608;
    const uint32_t* KH = QH + 9216;
    const uint32_t* KL = QH + 13824;

#pragma unroll
    for (int s = 0; s < 4; ++s) {
        uint32_t ah[4][4], al[4][4], bh[4][2], bl[4][2];
#pragma unroll
        for (int mt = 0; mt < 4; ++mt) {
            int r = wm * 64 + mt * 16 + lr;
            int w0 = r * 36 + s * 8 + lk, w1 = (r + 8) * 36 + s * 8 + lk;
            ah[mt][0] = QH[w0]; ah[mt][1] = QH[w1];
            ah[mt][2] = QH[w0 + 4]; ah[mt][3] = QH[w1 + 4];
            al[mt][0] = QL[w0]; al[mt][1] = QL[w1];
            al[mt][2] = QL[w0 + 4]; al[mt][3] = QL[w1 + 4];
        }
#pragma unroll
        for (int nt = 0; nt < 4; ++nt) {
            int cc = wn * 32 + nt * 8 + lr;
            int wv = cc * 36 + s * 8 + lk;
            bh[nt][0] = KH[wv]; bh[nt][1] = KH[wv + 4];
            bl[nt][0] = KL[wv]; bl[nt][1] = KL[wv + 4];
        }
#pragma unroll
        for (int mt = 0; mt < 4; ++mt)
#pragma unroll
            for (int nt = 0; nt < 4; ++nt) {
                float* cc = acc[mt * 4 + nt];
                mma_bf16(cc, ah[mt], bh[nt]);
                mma_bf16(cc, ah[mt], bl[nt]);
                mma_bf16(cc, al[mt], bh[nt]);
            }
    }
    __syncthreads();

    // stage to smem, then masked coalesced store
    float* sD = (float*)sm;   // 128 x 132
#pragma unroll
    for (int mt = 0; mt < 4; ++mt)
#pragma unroll
        for (int nt = 0; nt < 4; ++nt) {
            int col = wn * 32 + nt * 8 + lc2;
            const float* a = acc[mt * 4 + nt];
#pragma unroll
            for (int hf = 0; hf < 2; ++hf) {
                int r = wm * 64 + mt * 16 + lr + hf * 8;
                *(float2*)&sD[r * 132 + col] = make_float2(a[hf * 2], a[hf * 2 + 1]);
            }
        }
    __syncthreads();

    const unsigned char* cmb = g_cmb + (size_t)b * S_ * S_;
    float* ap = attn_g + (size_t)z * S_ * S_;
    for (int e = tid; e < 4096; e += 256) {
        int row = e >> 5, c4 = (e & 31) * 4;
        int q = m0 + row, k = n0 + c4;
        float4 v = *(float4*)&sD[row * 132 + c4];
        uchar4 f = *(const uchar4*)&cmb[(size_t)q * S_ + k];
        if (f.x) v.x = -1.0e9f;
        if (f.y) v.y = -1.0e9f;
        if (f.z) v.z = -1.0e9f;
        if (f.w) v.w = -1.0e9f;
        *(float4*)&ap[(size_t)q * S_ + k] = v;
    }
}

// ---------------------------------------------------------------------------
// av_mma: per z, ctx[128(q) x 64(d)] = attn @ V, K=2048 in chunks of 64.
// Warps 4(m) x 2(n), warp tile 32x32.
// smem: STG (2 x 128x68 f32), VT (2 x (VH+VL) 64x72 halves), AH/AL 128x72.
// ---------------------------------------------------------------------------
static constexpr int AV_STG0 = 0;
static constexpr int AV_VT0  = 2 * 34816;                  // 69632
static constexpr int AV_AH   = AV_VT0 + 2 * 18432;         // 106496
static constexpr int AV_AL   = AV_AH + 18432;              // 124928
static constexpr int AV_SMEM = AV_AL + 18432;              // 143360

__global__ __launch_bounds__(256) void av_mma(const float* __restrict__ attn_g)
{
    extern __shared__ __align__(16) char sm[];
    uint32_t sb = s2u(sm);
    const int tid = threadIdx.x, lane = tid & 31, w = tid >> 5;
    const int wm = w >> 1, wn = w & 1;
    const int m0 = blockIdx.x * 128, z = blockIdx.y;
    const int lr = lane >> 2, lk = lane & 3, lc2 = (lane & 3) * 2;

    const float* Ag = attn_g + (size_t)z * S_ * S_;
    const __nv_bfloat16* Vh = g_Vthi + (size_t)z * DK_ * S_;
    const __nv_bfloat16* Vl = g_Vtlo + (size_t)z * DK_ * S_;

    float acc[8][4];
#pragma unroll
    for (int i = 0; i < 8; ++i)
#pragma unroll
        for (int j = 0; j < 4; ++j) acc[i][j] = 0.f;

    auto prefetch = [&](int c) {
        int k0 = c * 64;
        int bi = c & 1;
#pragma unroll
        for (int i = 0; i < 12; ++i) {
            int g = tid + i * 256;
            if (g < 2048) {
                int row = g >> 4, c16 = g & 15;
                uint32_t dst = sb + AV_STG0 + (uint32_t)bi * 34816 + row * 272 + c16 * 16;
                cp16(dst, Ag + (size_t)(m0 + row) * S_ + k0 + c16 * 4);
            } else {
                int g2 = g - 2048;
                int t = g2 >> 9, idx = g2 & 511;
                int row = idx >> 3, gc = idx & 7;
                uint32_t dst = sb + AV_VT0 + (uint32_t)bi * 18432 + (uint32_t)t * 9216 +
                               row * 144 + gc * 16;
                cp16(dst, (t ? Vl : Vh) + (size_t)row * S_ + k0 + gc * 8);
            }
        }
        cp_commit();
    };

    prefetch(0);
    for (int c = 0; c < 32; ++c) {
        if (c + 1 < 32) { prefetch(c + 1); cp_wait1(); }
        else            { cp_wait0(); }
        __syncthreads();
        // convert staged fp32 attn -> bf16 hi/lo
        {
            const float* st = (const float*)(sm + AV_STG0 + (c & 1) * 34816);
            int r = tid >> 1, cbase = (tid & 1) * 32;
            uint32_t* AH = (uint32_t*)(sm + AV_AH);
            uint32_t* AL = (uint32_t*)(sm + AV_AL);
#pragma unroll
            for (int c4 = 0; c4 < 32; c4 += 4) {
                float4 v = *(const float4*)&st[r * 68 + cbase + c4];
                __nv_bfloat16 h0, h1, h2, h3, l0, l1, l2, l3;
                bsplit(v.x, h0, l0); bsplit(v.y, h1, l1);
                bsplit(v.z, h2, l2); bsplit(v.w, h3, l3);
                int wbase = r * 36 + (cbase + c4) / 2;
                AH[wbase]     = pack2(h0, h1);
                AH[wbase + 1] = pack2(h2, h3);
                AL[wbase]     = pack2(l0, l1);
                AL[wbase + 1] = pack2(l2, l3);
            }
        }
        __syncthreads();

        const uint32_t* AH = (const uint32_t*)(sm + AV_AH);
        const uint32_t* AL = (const uint32_t*)(sm + AV_AL);
        const uint32_t* VH = (const uint32_t*)(sm + AV_VT0 + (c & 1) * 18432);
        const uint32_t* VL = VH + 2304;
#pragma unroll
        for (int s = 0; s < 4; ++s) {
            uint32_t ah[2][4], al[2][4], bh[4][2], bl[4][2];
#pragma unroll
            for (int mt = 0; mt < 2; ++mt) {
                int r = wm * 32 + mt * 16 + lr;
                int w0 = r * 36 + s * 8 + lk, w1 = (r + 8) * 36 + s * 8 + lk;
                ah[mt][0] = AH[w0]; ah[mt][1] = AH[w1];
                ah[mt][2] = AH[w0 + 4]; ah[mt][3] = AH[w1 + 4];
                al[mt][0] = AL[w0]; al[mt][1] = AL[w1];
                al[mt][2] = AL[w0 + 4]; al[mt][3] = AL[w1 + 4];
            }
#pragma unroll
            for (int nt = 0; nt < 4; ++nt) {
                int cc = wn * 32 + nt * 8 + lr;
                int wv = cc * 36 + s * 8 + lk;
                bh[nt][0] = VH[wv]; bh[nt][1] = VH[wv + 4];
                bl[nt][0] = VL[wv]; bl[nt][1] = VL[wv + 4];
            }
#pragma unroll
            for (int mt = 0; mt < 2; ++mt)
#pragma unroll
                for (int nt = 0; nt < 4; ++nt) {
                    float* cc = acc[mt * 4 + nt];
                    mma_bf16(cc, ah[mt], bh[nt]);
                    mma_bf16(cc, ah[mt], bl[nt]);
                    mma_bf16(cc, al[mt], bh[nt]);
                }
        }
        __syncthreads();
    }

    // epilogue: split ctx -> g_Xhi/g_Xlo in (S,B,D) token layout
    const int bb = z >> 4, h = z & 15;
#pragma unroll
    for (int mt = 0; mt < 2; ++mt)
#pragma unroll
        for (int nt = 0; nt < 4; ++nt) {
            int d = wn * 32 + nt * 8 + lc2;
            const float* a = acc[mt * 4 + nt];
#pragma unroll
            for (int hf = 0; hf < 2; ++hf) {
                int q = m0 + wm * 32 + mt * 16 + lr + hf * 8;
                size_t o = ((size_t)q * B_ + bb) * D_ + h * DK_ + d;
                __nv_bfloat16 h0, h1, l0, l1;
                bsplit(a[hf * 2 + 0], h0, l0);
                bsplit(a[hf * 2 + 1], h1, l1);
                *(__nv_bfloat162*)&g_Xhi[o] = bf2(h0, h1);
                *(__nv_bfloat162*)&g_Xlo[o] = bf2(l0, l1);
            }
        }
}

// ---------------------------------------------------------------------------
// Row softmax, in place
// ---------------------------------------------------------------------------
__global__ __launch_bounds__(256) void softmax_kernel(float* __restrict__ attn)
{
    const size_t row = blockIdx.x;
    float* p = attn + row * (size_t)S_;
    const int tid = threadIdx.x;

    float v[8];
    *(float4*)&v[0] = *(const float4*)&p[tid * 8];
    *(float4*)&v[4] = *(const float4*)&p[tid * 8 + 4];

    float mx = v[0];
#pragma unroll
    for (int i = 1; i < 8; ++i) mx = fmaxf(mx, v[i]);
#pragma unroll
    for (int o = 16; o; o >>= 1) mx = fmaxf(mx, __shfl_xor_sync(0xffffffffu, mx, o));

    __shared__ float sred[8];
    const int warp = tid >> 5, lane = tid & 31;
    if (lane == 0) sred[warp] = mx;
    __syncthreads();
    if (tid == 0) {
        float m = sred[0];
#pragma unroll
        for (int i = 1; i < 8; ++i) m = fmaxf(m, sred[i]);
        sred[0] = m;
    }
    __syncthreads();
    mx = sred[0];

    float sum = 0.f;
#pragma unroll
    for (int i = 0; i < 8; ++i) { v[i] = __expf(v[i] - mx); sum += v[i]; }
#pragma unroll
    for (int o = 16; o; o >>= 1) sum += __shfl_xor_sync(0xffffffffu, sum, o);
    __syncthreads();
    if (lane == 0) sred[warp] = sum;
    __syncthreads();
    if (tid == 0) {
        float s = 0.f;
#pragma unroll
        for (int i = 0; i < 8; ++i) s += sred[i];
        sred[0] = s;
    }
    __syncthreads();
    const float inv = 1.0f / sred[0];

#pragma unroll
    for (int i = 0; i < 8; ++i) v[i] *= inv;
    *(float4*)&p[tid * 8]     = *(float4*)&v[0];
    *(float4*)&p[tid * 8 + 4] = *(float4*)&v[4];
}

// ---------------------------------------------------------------------------
extern "C" void kernel_launch(void* const* d_in, const int* in_sizes, int n_in,
                              void* d_out, int out_size)
{
    (void)in_sizes; (void)n_in; (void)out_size;
    const float* query = (const float*)d_in[0];
    const float* key   = (const float*)d_in[1];
    const float* value = (const float*)d_in[2];
    const int*   mask  = (const int*)d_in[3];
    const int*   kpm   = (const int*)d_in[4];
    const float* Wq    = (const float*)d_in[5];
    const float* Wk    = (const float*)d_in[6];
    const float* Wv    = (const float*)d_in[7];
    const float* Wo    = (const float*)d_in[8];
    const float* bo    = (const float*)d_in[9];

    float* out  = (float*)d_out;
    float* attn = out + (size_t)S_ * B_ * D_;   // tuple: (out, attn)

    cudaFuncSetAttribute(proj_mma,   cudaFuncAttributeMaxDynamicSharedMemorySize, PROJ_SMEM);
    cudaFuncSetAttribute(scores_mma, cudaFuncAttributeMaxDynamicSharedMemorySize, SC_SMEM);
    cudaFuncSetAttribute(av_mma,     cudaFuncAttributeMaxDynamicSharedMemorySize, AV_SMEM);

    const int n4x = R_ * D_ / 4;
    const int n4w = D_ * D_ / 4;

    mask_cmb<<<dim3(S_ * S_ / 1024, B_), 256>>>(mask, kpm);

    dim3 pgrid(D_ / 128, R_ / 128);  // (8, 32)

    conv_split<<<n4x / 256, 256>>>(query, 0, n4x);
    conv_split<<<n4w / 256, 256>>>(Wq, 1, n4w);
    proj_mma<<<pgrid, 256, PROJ_SMEM>>>(nullptr, nullptr, 0.125f, 0);

    conv_split<<<n4x / 256, 256>>>(key, 0, n4x);
    conv_split<<<n4w / 256, 256>>>(Wk, 1, n4w);
    proj_mma<<<pgrid, 256, PROJ_SMEM>>>(nullptr, nullptr, 1.0f, 1);

    conv_split<<<n4x / 256, 256>>>(value, 0, n4x);
    conv_split<<<n4w / 256, 256>>>(Wv, 1, n4w);
    proj_mma<<<pgrid, 256, PROJ_SMEM>>>(nullptr, nullptr, 1.0f, 2);

    scores_mma<<<dim3(S_ / 128, S_ / 128, Z_), 256, SC_SMEM>>>(attn);
    softmax_kernel<<<Z_ * S_, 256>>>(attn);
    av_mma<<<dim3(S_ / 128, Z_), 256, AV_SMEM>>>(attn);

    conv_split<<<n4w / 256, 256>>>(Wo, 1, n4w);
    proj_mma<<<pgrid, 256, PROJ_SMEM>>>(bo, out, 1.0f, 3);
}

// round 9
// speedup vs baseline: 1.8501x; 1.1650x over previous
#include <cuda_runtime.h>
#include <cuda_bf16.h>
#include <cstdint>

static constexpr int S_  = 2048;
static constexpr int B_  = 2;
static constexpr int D_  = 1024;
static constexpr int H_  = 16;
static constexpr int DK_ = 64;
static constexpr int R_  = S_ * B_;     // 4096 token rows
static constexpr int Z_  = B_ * H_;     // 32 (b,h) planes

// ---------------------------------------------------------------------------
// Device-global scratch (no allocations allowed)
// ---------------------------------------------------------------------------
__device__ __nv_bfloat16 g_Xhi[(size_t)R_ * D_];
__device__ __nv_bfloat16 g_Xlo[(size_t)R_ * D_];
__device__ __nv_bfloat16 g_Whi[(size_t)D_ * D_];
__device__ __nv_bfloat16 g_Wlo[(size_t)D_ * D_];
__device__ __nv_bfloat16 g_Qhi[(size_t)Z_ * S_ * DK_];
__device__ __nv_bfloat16 g_Qlo[(size_t)Z_ * S_ * DK_];
__device__ __nv_bfloat16 g_Khi[(size_t)Z_ * S_ * DK_];
__device__ __nv_bfloat16 g_Klo[(size_t)Z_ * S_ * DK_];
__device__ __nv_bfloat16 g_Vthi[(size_t)Z_ * DK_ * S_];   // (z, d, s)
__device__ __nv_bfloat16 g_Vtlo[(size_t)Z_ * DK_ * S_];
__device__ unsigned char g_cmb[(size_t)B_ * S_ * S_];     // 1 = masked
__device__ float g_mx[(size_t)Z_ * S_];                   // row max of raw scores
__device__ float g_inv[(size_t)Z_ * S_];                  // 1 / sum exp

// ---------------------------------------------------------------------------
// helpers
// ---------------------------------------------------------------------------
__device__ __forceinline__ uint32_t s2u(const void* p) {
    uint32_t a;
    asm("{ .reg .u64 t; cvta.to.shared.u64 t, %1; cvt.u32.u64 %0, t; }"
        : "=r"(a) : "l"(p));
    return a;
}
__device__ __forceinline__ void cp16(uint32_t d, const void* s) {
    asm volatile(
        "{ .reg .u64 g; cvta.to.global.u64 g, %1; "
        "cp.async.cg.shared.global [%0], [g], 16; }"
        :: "r"(d), "l"(s));
}
__device__ __forceinline__ void cp_commit() {
    asm volatile("cp.async.commit_group;" ::: "memory");
}
__device__ __forceinline__ void cp_wait0() {
    asm volatile("cp.async.wait_group 0;" ::: "memory");
}
__device__ __forceinline__ void cp_wait1() {
    asm volatile("cp.async.wait_group 1;" ::: "memory");
}

__device__ __forceinline__ void mma_bf16(float* c, const uint32_t* a, const uint32_t* b)
{
    asm volatile(
        "mma.sync.aligned.m16n8k16.row.col.f32.bf16.bf16.f32 "
        "{%0,%1,%2,%3}, {%4,%5,%6,%7}, {%8,%9}, {%0,%1,%2,%3};"
        : "+f"(c[0]), "+f"(c[1]), "+f"(c[2]), "+f"(c[3])
        : "r"(a[0]), "r"(a[1]), "r"(a[2]), "r"(a[3]), "r"(b[0]), "r"(b[1]));
}

__device__ __forceinline__ void bsplit(float v, __nv_bfloat16& h, __nv_bfloat16& l) {
    h = __float2bfloat16(v);
    l = __float2bfloat16(v - __bfloat162float(h));
}
__device__ __forceinline__ __nv_bfloat162 bf2(__nv_bfloat16 a, __nv_bfloat16 b) {
    __nv_bfloat162 t; t.x = a; t.y = b; return t;
}
__device__ __forceinline__ uint32_t pack2(__nv_bfloat16 a, __nv_bfloat16 b) {
    return (uint32_t)__bfloat16_as_ushort(a) |
           ((uint32_t)__bfloat16_as_ushort(b) << 16);
}

// ---------------------------------------------------------------------------
// fp32 -> bf16 hi/lo split.  sel 0: g_X*, sel 1: g_W*
// ---------------------------------------------------------------------------
__global__ __launch_bounds__(256) void conv_split(const float* __restrict__ src,
                                                  int sel, int n4)
{
    __nv_bfloat16* hi = sel ? g_Whi : g_Xhi;
    __nv_bfloat16* lo = sel ? g_Wlo : g_Xlo;
    int i = blockIdx.x * 256 + threadIdx.x;
    if (i >= n4) return;
    float4 v = ((const float4*)src)[i];
    __nv_bfloat16 h0, h1, h2, h3, l0, l1, l2, l3;
    bsplit(v.x, h0, l0); bsplit(v.y, h1, l1);
    bsplit(v.z, h2, l2); bsplit(v.w, h3, l3);
    ((__nv_bfloat162*)hi)[i * 2]     = bf2(h0, h1);
    ((__nv_bfloat162*)hi)[i * 2 + 1] = bf2(h2, h3);
    ((__nv_bfloat162*)lo)[i * 2]     = bf2(l0, l1);
    ((__nv_bfloat162*)lo)[i * 2 + 1] = bf2(l2, l3);
}

// combined mask flags: cmb[b][q][k] = (mask==0 || kpm==0)
__global__ __launch_bounds__(256) void mask_cmb(const int* __restrict__ mask,
                                                const int* __restrict__ kpm)
{
    int b = blockIdx.y;
    size_t i = (size_t)blockIdx.x * 256 + threadIdx.x;   // per uchar4
    int q  = (int)(i >> 9);
    int k4 = (int)(i & 511) << 2;
    int4 m  = *(const int4*)&mask[(size_t)q * S_ + k4];
    int4 kp = *(const int4*)&kpm[(size_t)b * S_ + k4];
    uchar4 r;
    r.x = (m.x == 0 || kp.x == 0); r.y = (m.y == 0 || kp.y == 0);
    r.z = (m.z == 0 || kp.z == 0); r.w = (m.w == 0 || kp.w == 0);
    *(uchar4*)&g_cmb[((size_t)b * S_ + q) * S_ + k4] = r;
}

// ---------------------------------------------------------------------------
// proj_mma: C[4096,1024] = X @ W^T, tile 128x128, BK=32, warps 2(m)x4(n).
//  mode 0: -> g_Qhi/lo (scale 1/8)   mode 1: -> g_Khi/lo
//  mode 2: -> g_Vthi/lo (transposed) mode 3: -> outp (fp32 + bias)
// ---------------------------------------------------------------------------
static constexpr int PROJ_SMEM = 2 * 4 * 128 * 80;   // 81920

__global__ __launch_bounds__(256, 2) void proj_mma(const float* __restrict__ bias,
                                                   float* __restrict__ outp,
                                                   float scale, int mode)
{
    extern __shared__ __align__(16) char sm[];
    uint32_t sb = s2u(sm);
    const int tid = threadIdx.x, lane = tid & 31, w = tid >> 5;
    const int wm = w >> 2, wn = w & 3;
    const int m0 = blockIdx.y * 128, n0 = blockIdx.x * 128;
    const int lr = lane >> 2, lk = lane & 3, lc2 = (lane & 3) * 2;

    const __nv_bfloat16* srcs[4] = { g_Xhi, g_Xlo, g_Whi, g_Wlo };

    float acc[16][4];
#pragma unroll
    for (int i = 0; i < 16; ++i)
#pragma unroll
        for (int j = 0; j < 4; ++j) acc[i][j] = 0.f;

    auto prefetch = [&](int c) {
        int k0 = c * 32;
        uint32_t bufb = sb + (uint32_t)(c & 1) * 40960;
#pragma unroll
        for (int i = 0; i < 8; ++i) {
            int g = tid + i * 256;
            int t = g >> 9, idx = g & 511;
            int row = idx >> 2, gc = idx & 3;
            int grow = ((t < 2) ? m0 : n0) + row;
            uint32_t dst = bufb + (uint32_t)t * 10240 + row * 80 + gc * 16;
            cp16(dst, srcs[t] + (size_t)grow * D_ + k0 + gc * 8);
        }
        cp_commit();
    };

    prefetch(0);
    for (int c = 0; c < 32; ++c) {
        if (c + 1 < 32) { prefetch(c + 1); cp_wait1(); }
        else            { cp_wait0(); }
        __syncthreads();
        const uint32_t* XH = (const uint32_t*)(sm + (c & 1) * 40960);
        const uint32_t* XL = XH + 2560;
        const uint32_t* WH = XH + 5120;
        const uint32_t* WL = XH + 7680;
#pragma unroll
        for (int s = 0; s < 2; ++s) {
            uint32_t ah[4][4], al[4][4], bh[4][2], bl[4][2];
#pragma unroll
            for (int mt = 0; mt < 4; ++mt) {
                int r = wm * 64 + mt * 16 + lr;
                int w0 = r * 20 + s * 8 + lk, w1 = (r + 8) * 20 + s * 8 + lk;
                ah[mt][0] = XH[w0]; ah[mt][1] = XH[w1];
                ah[mt][2] = XH[w0 + 4]; ah[mt][3] = XH[w1 + 4];
                al[mt][0] = XL[w0]; al[mt][1] = XL[w1];
                al[mt][2] = XL[w0 + 4]; al[mt][3] = XL[w1 + 4];
            }
#pragma unroll
            for (int nt = 0; nt < 4; ++nt) {
                int cc = wn * 32 + nt * 8 + lr;
                int wv = cc * 20 + s * 8 + lk;
                bh[nt][0] = WH[wv]; bh[nt][1] = WH[wv + 4];
                bl[nt][0] = WL[wv]; bl[nt][1] = WL[wv + 4];
            }
#pragma unroll
            for (int mt = 0; mt < 4; ++mt)
#pragma unroll
                for (int nt = 0; nt < 4; ++nt) {
                    float* cc = acc[mt * 4 + nt];
                    mma_bf16(cc, ah[mt], bh[nt]);
                    mma_bf16(cc, ah[mt], bl[nt]);
                    mma_bf16(cc, al[mt], bh[nt]);
                }
        }
        __syncthreads();
    }

    // ---- epilogue ----
    if (mode <= 1) {
        __nv_bfloat16* Chi = mode ? g_Khi : g_Qhi;
        __nv_bfloat16* Clo = mode ? g_Klo : g_Qlo;
#pragma unroll
        for (int mt = 0; mt < 4; ++mt)
#pragma unroll
            for (int nt = 0; nt < 4; ++nt) {
                int col = n0 + wn * 32 + nt * 8 + lc2;
                int h = col >> 6, d = col & 63;
                const float* a = acc[mt * 4 + nt];
#pragma unroll
                for (int hf = 0; hf < 2; ++hf) {
                    int r = m0 + wm * 64 + mt * 16 + lr + hf * 8;
                    int ss = r >> 1, bb = r & 1;
                    float v0 = a[hf * 2 + 0] * scale;
                    float v1 = a[hf * 2 + 1] * scale;
                    __nv_bfloat16 h0, h1, l0, l1;
                    bsplit(v0, h0, l0); bsplit(v1, h1, l1);
                    size_t o = (((size_t)(bb * H_ + h)) * S_ + ss) * DK_ + d;
                    *(__nv_bfloat162*)&Chi[o] = bf2(h0, h1);
                    *(__nv_bfloat162*)&Clo[o] = bf2(l0, l1);
                }
            }
    } else if (mode == 3) {
#pragma unroll
        for (int mt = 0; mt < 4; ++mt)
#pragma unroll
            for (int nt = 0; nt < 4; ++nt) {
                int col = n0 + wn * 32 + nt * 8 + lc2;
                float b0 = bias[col], b1 = bias[col + 1];
                const float* a = acc[mt * 4 + nt];
#pragma unroll
                for (int hf = 0; hf < 2; ++hf) {
                    int r = m0 + wm * 64 + mt * 16 + lr + hf * 8;
                    float2 v;
                    v.x = a[hf * 2 + 0] + b0;
                    v.y = a[hf * 2 + 1] + b1;
                    *(float2*)&outp[(size_t)r * D_ + col] = v;
                }
            }
    } else {  // mode 2: V -> transposed g_Vt (stage fp32 in smem, scatter)
        float* sD = (float*)sm;   // 128 x 132
#pragma unroll
        for (int mt = 0; mt < 4; ++mt)
#pragma unroll
            for (int nt = 0; nt < 4; ++nt) {
                int col = wn * 32 + nt * 8 + lc2;
                const float* a = acc[mt * 4 + nt];
#pragma unroll
                for (int hf = 0; hf < 2; ++hf) {
                    int r = wm * 64 + mt * 16 + lr + hf * 8;
                    float2 v = make_float2(a[hf * 2 + 0], a[hf * 2 + 1]);
                    *(float2*)&sD[r * 132 + col] = v;
                }
            }
        __syncthreads();
        for (int e = tid; e < 16384; e += 256) {
            int row = e & 127, col = e >> 7;
            float v = sD[row * 132 + col];
            int tok = m0 + row;
            int ss = tok >> 1, bb = tok & 1;
            int gc = n0 + col;
            int h = gc >> 6, d = gc & 63;
            __nv_bfloat16 hh, ll;
            bsplit(v, hh, ll);
            size_t o = ((size_t)(bb * H_ + h) * DK_ + d) * S_ + ss;
            g_Vthi[o] = hh;
            g_Vtlo[o] = ll;
        }
    }
}

// ---------------------------------------------------------------------------
// scores_mma: per z, 128(q) x 128(k) tile of Q.K^T (K=64), masks, -> attn raw.
// ---------------------------------------------------------------------------
static constexpr int SC_SMEM = 4 * 128 * 144;        // 73728

__global__ __launch_bounds__(256, 2) void scores_mma(float* __restrict__ attn_g)
{
    extern __shared__ __align__(16) char sm[];
    uint32_t sb = s2u(sm);
    const int tid = threadIdx.x, lane = tid & 31, w = tid >> 5;
    const int wm = w >> 2, wn = w & 3;
    const int n0 = blockIdx.x * 128, m0 = blockIdx.y * 128, z = blockIdx.z;
    const int b = z >> 4;
    const int lr = lane >> 2, lk = lane & 3, lc2 = (lane & 3) * 2;

    const size_t zoff = (size_t)z * S_ * DK_;
    const __nv_bfloat16* srcs[4] = { g_Qhi + zoff, g_Qlo + zoff,
                                     g_Khi + zoff, g_Klo + zoff };
#pragma unroll
    for (int i = 0; i < 16; ++i) {
        int g = tid + i * 256;
        int t = g >> 10, idx = g & 1023;
        int row = idx >> 3, gc = idx & 7;
        int grow = ((t < 2) ? m0 : n0) + row;
        uint32_t dst = sb + (uint32_t)t * 18432 + row * 144 + gc * 16;
        cp16(dst, srcs[t] + (size_t)grow * DK_ + gc * 8);
    }
    cp_commit();
    cp_wait0();
    __syncthreads();

    float acc[16][4];
#pragma unroll
    for (int i = 0; i < 16; ++i)
#pragma unroll
        for (int j = 0; j < 4; ++j) acc[i][j] = 0.f;

    const uint32_t* QH = (const uint32_t*)sm;
    const uint32_t* QL = QH + 4608;
    const uint32_t* KH = QH + 9216;
    const uint32_t* KL = QH + 13824;

#pragma unroll
    for (int s = 0; s < 4; ++s) {
        uint32_t ah[4][4], al[4][4], bh[4][2], bl[4][2];
#pragma unroll
        for (int mt = 0; mt < 4; ++mt) {
            int r = wm * 64 + mt * 16 + lr;
            int w0 = r * 36 + s * 8 + lk, w1 = (r + 8) * 36 + s * 8 + lk;
            ah[mt][0] = QH[w0]; ah[mt][1] = QH[w1];
            ah[mt][2] = QH[w0 + 4]; ah[mt][3] = QH[w1 + 4];
            al[mt][0] = QL[w0]; al[mt][1] = QL[w1];
            al[mt][2] = QL[w0 + 4]; al[mt][3] = QL[w1 + 4];
        }
#pragma unroll
        for (int nt = 0; nt < 4; ++nt) {
            int cc = wn * 32 + nt * 8 + lr;
            int wv = cc * 36 + s * 8 + lk;
            bh[nt][0] = KH[wv]; bh[nt][1] = KH[wv + 4];
            bl[nt][0] = KL[wv]; bl[nt][1] = KL[wv + 4];
        }
#pragma unroll
        for (int mt = 0; mt < 4; ++mt)
#pragma unroll
            for (int nt = 0; nt < 4; ++nt) {
                float* cc = acc[mt * 4 + nt];
                mma_bf16(cc, ah[mt], bh[nt]);
                mma_bf16(cc, ah[mt], bl[nt]);
                mma_bf16(cc, al[mt], bh[nt]);
            }
    }
    __syncthreads();

    // stage to smem, then masked coalesced store (raw scores)
    float* sD = (float*)sm;   // 128 x 132
#pragma unroll
    for (int mt = 0; mt < 4; ++mt)
#pragma unroll
        for (int nt = 0; nt < 4; ++nt) {
            int col = wn * 32 + nt * 8 + lc2;
            const float* a = acc[mt * 4 + nt];
#pragma unroll
            for (int hf = 0; hf < 2; ++hf) {
                int r = wm * 64 + mt * 16 + lr + hf * 8;
                *(float2*)&sD[r * 132 + col] = make_float2(a[hf * 2], a[hf * 2 + 1]);
            }
        }
    __syncthreads();

    const unsigned char* cmb = g_cmb + (size_t)b * S_ * S_;
    float* ap = attn_g + (size_t)z * S_ * S_;
    for (int e = tid; e < 4096; e += 256) {
        int row = e >> 5, c4 = (e & 31) * 4;
        int q = m0 + row, k = n0 + c4;
        float4 v = *(float4*)&sD[row * 132 + c4];
        uchar4 f = *(const uchar4*)&cmb[(size_t)q * S_ + k];
        if (f.x) v.x = -1.0e9f;
        if (f.y) v.y = -1.0e9f;
        if (f.z) v.z = -1.0e9f;
        if (f.w) v.w = -1.0e9f;
        *(float4*)&ap[(size_t)q * S_ + k] = v;
    }
}

// ---------------------------------------------------------------------------
// stats_kernel: per row, max + 1/sum(exp(s-max)) of raw scores
// ---------------------------------------------------------------------------
__global__ __launch_bounds__(256) void stats_kernel(const float* __restrict__ attn)
{
    const size_t row = blockIdx.x;
    const float* p = attn + row * (size_t)S_;
    const int tid = threadIdx.x;

    float v[8];
    *(float4*)&v[0] = *(const float4*)&p[tid * 8];
    *(float4*)&v[4] = *(const float4*)&p[tid * 8 + 4];

    float mx = v[0];
#pragma unroll
    for (int i = 1; i < 8; ++i) mx = fmaxf(mx, v[i]);
#pragma unroll
    for (int o = 16; o; o >>= 1) mx = fmaxf(mx, __shfl_xor_sync(0xffffffffu, mx, o));

    __shared__ float sred[8];
    const int warp = tid >> 5, lane = tid & 31;
    if (lane == 0) sred[warp] = mx;
    __syncthreads();
    if (tid == 0) {
        float m = sred[0];
#pragma unroll
        for (int i = 1; i < 8; ++i) m = fmaxf(m, sred[i]);
        sred[0] = m;
    }
    __syncthreads();
    mx = sred[0];

    float sum = 0.f;
#pragma unroll
    for (int i = 0; i < 8; ++i) sum += __expf(v[i] - mx);
#pragma unroll
    for (int o = 16; o; o >>= 1) sum += __shfl_xor_sync(0xffffffffu, sum, o);
    __syncthreads();
    if (lane == 0) sred[warp] = sum;
    __syncthreads();
    if (tid == 0) {
        float s = 0.f;
#pragma unroll
        for (int i = 0; i < 8; ++i) s += sred[i];
        g_mx[row]  = mx;
        g_inv[row] = 1.0f / s;
    }
}

// ---------------------------------------------------------------------------
// av_mma: per z, ctx[64(q) x 64(d)] = softmax(raw) @ V, K=2048 chunks of 64.
// Reads raw scores, computes p = exp(s-mx)*inv in registers, writes p back
// to attn (final output), converts p to bf16 hi/lo for mma.
// Warps: wm = w>>1 (0..3, 16 rows), wn = w&1 (0..1, 32 cols).
// smem: STG 2 x 64x68 f32 (17408 ea), VT 2 x 18432, AH 9216, AL 9216.
// ---------------------------------------------------------------------------
static constexpr int AV_STG0 = 0;
static constexpr int AV_VT0  = 2 * 17408;                  // 34816
static constexpr int AV_AH   = AV_VT0 + 2 * 18432;         // 71680
static constexpr int AV_AL   = AV_AH + 9216;               // 80896
static constexpr int AV_SMEM = AV_AL + 9216;               // 90112

__global__ __launch_bounds__(256, 2) void av_mma(float* __restrict__ attn_g)
{
    extern __shared__ __align__(16) char sm[];
    uint32_t sb = s2u(sm);
    const int tid = threadIdx.x, lane = tid & 31, w = tid >> 5;
    const int wm = w >> 1, wn = w & 1;
    const int m0 = blockIdx.x * 64, z = blockIdx.y;
    const int lr = lane >> 2, lk = lane & 3, lc2 = (lane & 3) * 2;

    float* Ag = attn_g + (size_t)z * S_ * S_;
    const __nv_bfloat16* Vh = g_Vthi + (size_t)z * DK_ * S_;
    const __nv_bfloat16* Vl = g_Vtlo + (size_t)z * DK_ * S_;

    float acc[4][4];
#pragma unroll
    for (int i = 0; i < 4; ++i)
#pragma unroll
        for (int j = 0; j < 4; ++j) acc[i][j] = 0.f;

    // per-thread row stats for the conversion stage
    const int cr = tid >> 2;                 // 0..63
    const int cb = (tid & 3) * 16;           // 0,16,32,48
    const float smx  = g_mx [(size_t)z * S_ + m0 + cr];
    const float sinv = g_inv[(size_t)z * S_ + m0 + cr];

    auto prefetch = [&](int c) {
        int k0 = c * 64;
        int bi = c & 1;
#pragma unroll
        for (int i = 0; i < 8; ++i) {
            int g = tid + i * 256;
            if (g < 1024) {
                int row = g >> 4, c16 = g & 15;
                uint32_t dst = sb + AV_STG0 + (uint32_t)bi * 17408 + row * 272 + c16 * 16;
                cp16(dst, Ag + (size_t)(m0 + row) * S_ + k0 + c16 * 4);
            } else {
                int g2 = g - 1024;
                int t = g2 >> 9, idx = g2 & 511;
                int row = idx >> 3, gc = idx & 7;
                uint32_t dst = sb + AV_VT0 + (uint32_t)bi * 18432 + (uint32_t)t * 9216 +
                               row * 144 + gc * 16;
                cp16(dst, (t ? Vl : Vh) + (size_t)row * S_ + k0 + gc * 8);
            }
        }
        cp_commit();
    };

    prefetch(0);
    for (int c = 0; c < 32; ++c) {
        if (c + 1 < 32) { prefetch(c + 1); cp_wait1(); }
        else            { cp_wait0(); }
        __syncthreads();
        // conversion: raw -> p, write p to gmem, split to bf16 hi/lo
        {
            const int k0 = c * 64;
            const float* st = (const float*)(sm + AV_STG0 + (c & 1) * 17408);
            uint32_t* AH = (uint32_t*)(sm + AV_AH);
            uint32_t* AL = (uint32_t*)(sm + AV_AL);
            float* prow = Ag + (size_t)(m0 + cr) * S_ + k0;
#pragma unroll
            for (int c4 = 0; c4 < 16; c4 += 4) {
                float4 v = *(const float4*)&st[cr * 68 + cb + c4];
                float4 p;
                p.x = __expf(v.x - smx) * sinv;
                p.y = __expf(v.y - smx) * sinv;
                p.z = __expf(v.z - smx) * sinv;
                p.w = __expf(v.w - smx) * sinv;
                *(float4*)&prow[cb + c4] = p;
                __nv_bfloat16 h0, h1, h2, h3, l0, l1, l2, l3;
                bsplit(p.x, h0, l0); bsplit(p.y, h1, l1);
                bsplit(p.z, h2, l2); bsplit(p.w, h3, l3);
                int wbase = cr * 36 + (cb + c4) / 2;
                AH[wbase]     = pack2(h0, h1);
                AH[wbase + 1] = pack2(h2, h3);
                AL[wbase]     = pack2(l0, l1);
                AL[wbase + 1] = pack2(l2, l3);
            }
        }
        __syncthreads();

        const uint32_t* AH = (const uint32_t*)(sm + AV_AH);
        const uint32_t* AL = (const uint32_t*)(sm + AV_AL);
        const uint32_t* VH = (const uint32_t*)(sm + AV_VT0 + (c & 1) * 18432);
        const uint32_t* VL = VH + 2304;
#pragma unroll
        for (int s = 0; s < 4; ++s) {
            uint32_t ah[4], al[4], bh[4][2], bl[4][2];
            {
                int r = wm * 16 + lr;
                int w0 = r * 36 + s * 8 + lk, w1 = (r + 8) * 36 + s * 8 + lk;
                ah[0] = AH[w0]; ah[1] = AH[w1];
                ah[2] = AH[w0 + 4]; ah[3] = AH[w1 + 4];
                al[0] = AL[w0]; al[1] = AL[w1];
                al[2] = AL[w0 + 4]; al[3] = AL[w1 + 4];
            }
#pragma unroll
            for (int nt = 0; nt < 4; ++nt) {
                int cc = wn * 32 + nt * 8 + lr;
                int wv = cc * 36 + s * 8 + lk;
                bh[nt][0] = VH[wv]; bh[nt][1] = VH[wv + 4];
                bl[nt][0] = VL[wv]; bl[nt][1] = VL[wv + 4];
            }
#pragma unroll
            for (int nt = 0; nt < 4; ++nt) {
                float* cc = acc[nt];
                mma_bf16(cc, ah, bh[nt]);
                mma_bf16(cc, ah, bl[nt]);
                mma_bf16(cc, al, bh[nt]);
            }
        }
        __syncthreads();
    }

    // epilogue: split ctx -> g_Xhi/g_Xlo in (S,B,D) token layout
    const int bb = z >> 4, h = z & 15;
#pragma unroll
    for (int nt = 0; nt < 4; ++nt) {
        int d = wn * 32 + nt * 8 + lc2;
        const float* a = acc[nt];
#pragma unroll
        for (int hf = 0; hf < 2; ++hf) {
            int q = m0 + wm * 16 + lr + hf * 8;
            size_t o = ((size_t)q * B_ + bb) * D_ + h * DK_ + d;
            __nv_bfloat16 h0, h1, l0, l1;
            bsplit(a[hf * 2 + 0], h0, l0);
            bsplit(a[hf * 2 + 1], h1, l1);
            *(__nv_bfloat162*)&g_Xhi[o] = bf2(h0, h1);
            *(__nv_bfloat162*)&g_Xlo[o] = bf2(l0, l1);
        }
    }
}

// ---------------------------------------------------------------------------
extern "C" void kernel_launch(void* const* d_in, const int* in_sizes, int n_in,
                              void* d_out, int out_size)
{
    (void)in_sizes; (void)n_in; (void)out_size;
    const float* query = (const float*)d_in[0];
    const float* key   = (const float*)d_in[1];
    const float* value = (const float*)d_in[2];
    const int*   mask  = (const int*)d_in[3];
    const int*   kpm   = (const int*)d_in[4];
    const float* Wq    = (const float*)d_in[5];
    const float* Wk    = (const float*)d_in[6];
    const float* Wv    = (const float*)d_in[7];
    const float* Wo    = (const float*)d_in[8];
    const float* bo    = (const float*)d_in[9];

    float* out  = (float*)d_out;
    float* attn = out + (size_t)S_ * B_ * D_;   // tuple: (out, attn)

    cudaFuncSetAttribute(proj_mma,   cudaFuncAttributeMaxDynamicSharedMemorySize, PROJ_SMEM);
    cudaFuncSetAttribute(scores_mma, cudaFuncAttributeMaxDynamicSharedMemorySize, SC_SMEM);
    cudaFuncSetAttribute(av_mma,     cudaFuncAttributeMaxDynamicSharedMemorySize, AV_SMEM);

    const int n4x = R_ * D_ / 4;
    const int n4w = D_ * D_ / 4;

    mask_cmb<<<dim3(S_ * S_ / 1024, B_), 256>>>(mask, kpm);

    dim3 pgrid(D_ / 128, R_ / 128);  // (8, 32)

    conv_split<<<n4x / 256, 256>>>(query, 0, n4x);
    conv_split<<<n4w / 256, 256>>>(Wq, 1, n4w);
    proj_mma<<<pgrid, 256, PROJ_SMEM>>>(nullptr, nullptr, 0.125f, 0);

    conv_split<<<n4x / 256, 256>>>(key, 0, n4x);
    conv_split<<<n4w / 256, 256>>>(Wk, 1, n4w);
    proj_mma<<<pgrid, 256, PROJ_SMEM>>>(nullptr, nullptr, 1.0f, 1);

    conv_split<<<n4x / 256, 256>>>(value, 0, n4x);
    conv_split<<<n4w / 256, 256>>>(Wv, 1, n4w);
    proj_mma<<<pgrid, 256, PROJ_SMEM>>>(nullptr, nullptr, 1.0f, 2);

    scores_mma<<<dim3(S_ / 128, S_ / 128, Z_), 256, SC_SMEM>>>(attn);
    stats_kernel<<<Z_ * S_, 256>>>(attn);
    av_mma<<<dim3(S_ / 64, Z_), 256, AV_SMEM>>>(attn);

    conv_split<<<n4w / 256, 256>>>(Wo, 1, n4w);
    proj_mma<<<pgrid, 256, PROJ_SMEM>>>(bo, out, 1.0f, 3);
}

// round 10
// speedup vs baseline: 1.9080x; 1.0313x over previous
#include <cuda_runtime.h>
#include <cuda_bf16.h>
#include <cstdint>

static constexpr int S_  = 2048;
static constexpr int B_  = 2;
static constexpr int D_  = 1024;
static constexpr int H_  = 16;
static constexpr int DK_ = 64;
static constexpr int R_  = S_ * B_;     // 4096 token rows
static constexpr int Z_  = B_ * H_;     // 32 (b,h) planes

// ---------------------------------------------------------------------------
// Device-global scratch.  X slots: 0=query/ctx, 1=key, 2=value.  W slots:
// 0=Wq, 1=Wk, 2=Wv, 3=Wo.
// ---------------------------------------------------------------------------
__device__ __nv_bfloat16 g_Xhi[(size_t)3 * R_ * D_];
__device__ __nv_bfloat16 g_Xlo[(size_t)3 * R_ * D_];
__device__ __nv_bfloat16 g_Whi[(size_t)4 * D_ * D_];
__device__ __nv_bfloat16 g_Wlo[(size_t)4 * D_ * D_];
__device__ __nv_bfloat16 g_Qhi[(size_t)Z_ * S_ * DK_];
__device__ __nv_bfloat16 g_Qlo[(size_t)Z_ * S_ * DK_];
__device__ __nv_bfloat16 g_Khi[(size_t)Z_ * S_ * DK_];
__device__ __nv_bfloat16 g_Klo[(size_t)Z_ * S_ * DK_];
__device__ __nv_bfloat16 g_Vthi[(size_t)Z_ * DK_ * S_];   // (z, d, s)
__device__ __nv_bfloat16 g_Vtlo[(size_t)Z_ * DK_ * S_];
__device__ unsigned char g_cmb[(size_t)B_ * S_ * S_];     // 1 = masked
__device__ float g_pm[(size_t)Z_ * S_ * 16];              // per-tile row max
__device__ float g_ps[(size_t)Z_ * S_ * 16];              // per-tile exp-sum
__device__ float g_mx[(size_t)Z_ * S_];                   // row max
__device__ float g_inv[(size_t)Z_ * S_];                  // 1 / sum exp

// ---------------------------------------------------------------------------
// helpers
// ---------------------------------------------------------------------------
__device__ __forceinline__ uint32_t s2u(const void* p) {
    uint32_t a;
    asm("{ .reg .u64 t; cvta.to.shared.u64 t, %1; cvt.u32.u64 %0, t; }"
        : "=r"(a) : "l"(p));
    return a;
}
__device__ __forceinline__ void cp16(uint32_t d, const void* s) {
    asm volatile(
        "{ .reg .u64 g; cvta.to.global.u64 g, %1; "
        "cp.async.cg.shared.global [%0], [g], 16; }"
        :: "r"(d), "l"(s));
}
__device__ __forceinline__ void cp_commit() {
    asm volatile("cp.async.commit_group;" ::: "memory");
}
__device__ __forceinline__ void cp_wait0() {
    asm volatile("cp.async.wait_group 0;" ::: "memory");
}
__device__ __forceinline__ void cp_wait1() {
    asm volatile("cp.async.wait_group 1;" ::: "memory");
}

__device__ __forceinline__ void mma_bf16(float* c, const uint32_t* a, const uint32_t* b)
{
    asm volatile(
        "mma.sync.aligned.m16n8k16.row.col.f32.bf16.bf16.f32 "
        "{%0,%1,%2,%3}, {%4,%5,%6,%7}, {%8,%9}, {%0,%1,%2,%3};"
        : "+f"(c[0]), "+f"(c[1]), "+f"(c[2]), "+f"(c[3])
        : "r"(a[0]), "r"(a[1]), "r"(a[2]), "r"(a[3]), "r"(b[0]), "r"(b[1]));
}

__device__ __forceinline__ void bsplit(float v, __nv_bfloat16& h, __nv_bfloat16& l) {
    h = __float2bfloat16(v);
    l = __float2bfloat16(v - __bfloat162float(h));
}
__device__ __forceinline__ __nv_bfloat162 bf2(__nv_bfloat16 a, __nv_bfloat16 b) {
    __nv_bfloat162 t; t.x = a; t.y = b; return t;
}
__device__ __forceinline__ uint32_t pack2(__nv_bfloat16 a, __nv_bfloat16 b) {
    return (uint32_t)__bfloat16_as_ushort(a) |
           ((uint32_t)__bfloat16_as_ushort(b) << 16);
}

// ---------------------------------------------------------------------------
// fp32 -> bf16 hi/lo splits (slotted)
// ---------------------------------------------------------------------------
__global__ __launch_bounds__(256) void conv_split_x(const float* __restrict__ q,
                                                    const float* __restrict__ k,
                                                    const float* __restrict__ v)
{
    const int z = blockIdx.y;
    const float* src = (z == 0) ? q : (z == 1) ? k : v;
    __nv_bfloat16* hi = g_Xhi + (size_t)z * R_ * D_;
    __nv_bfloat16* lo = g_Xlo + (size_t)z * R_ * D_;
    int i = blockIdx.x * 256 + threadIdx.x;   // over R*D/4
    float4 val = ((const float4*)src)[i];
    __nv_bfloat16 h0, h1, h2, h3, l0, l1, l2, l3;
    bsplit(val.x, h0, l0); bsplit(val.y, h1, l1);
    bsplit(val.z, h2, l2); bsplit(val.w, h3, l3);
    ((__nv_bfloat162*)hi)[i * 2]     = bf2(h0, h1);
    ((__nv_bfloat162*)hi)[i * 2 + 1] = bf2(h2, h3);
    ((__nv_bfloat162*)lo)[i * 2]     = bf2(l0, l1);
    ((__nv_bfloat162*)lo)[i * 2 + 1] = bf2(l2, l3);
}

__global__ __launch_bounds__(256) void conv_split_w(const float* __restrict__ wq,
                                                    const float* __restrict__ wk,
                                                    const float* __restrict__ wv,
                                                    const float* __restrict__ wo)
{
    const int z = blockIdx.y;
    const float* src = (z == 0) ? wq : (z == 1) ? wk : (z == 2) ? wv : wo;
    __nv_bfloat16* hi = g_Whi + (size_t)z * D_ * D_;
    __nv_bfloat16* lo = g_Wlo + (size_t)z * D_ * D_;
    int i = blockIdx.x * 256 + threadIdx.x;   // over D*D/4
    float4 val = ((const float4*)src)[i];
    __nv_bfloat16 h0, h1, h2, h3, l0, l1, l2, l3;
    bsplit(val.x, h0, l0); bsplit(val.y, h1, l1);
    bsplit(val.z, h2, l2); bsplit(val.w, h3, l3);
    ((__nv_bfloat162*)hi)[i * 2]     = bf2(h0, h1);
    ((__nv_bfloat162*)hi)[i * 2 + 1] = bf2(h2, h3);
    ((__nv_bfloat162*)lo)[i * 2]     = bf2(l0, l1);
    ((__nv_bfloat162*)lo)[i * 2 + 1] = bf2(l2, l3);
}

// combined mask flags: cmb[b][q][k] = (mask==0 || kpm==0)
__global__ __launch_bounds__(256) void mask_cmb(const int* __restrict__ mask,
                                                const int* __restrict__ kpm)
{
    int b = blockIdx.y;
    size_t i = (size_t)blockIdx.x * 256 + threadIdx.x;   // per uchar4
    int q  = (int)(i >> 9);
    int k4 = (int)(i & 511) << 2;
    int4 m  = *(const int4*)&mask[(size_t)q * S_ + k4];
    int4 kp = *(const int4*)&kpm[(size_t)b * S_ + k4];
    uchar4 r;
    r.x = (m.x == 0 || kp.x == 0); r.y = (m.y == 0 || kp.y == 0);
    r.z = (m.z == 0 || kp.z == 0); r.w = (m.w == 0 || kp.w == 0);
    *(uchar4*)&g_cmb[((size_t)b * S_ + q) * S_ + k4] = r;
}

// ---------------------------------------------------------------------------
// proj_mma: C[4096,1024] = X @ W^T, tile 128x128, BK=32, warps 2(m)x4(n).
//  mode 0: batched QKV (blockIdx.z selects slot; epilogue per slot)
//  mode 3: ctx (X slot 0) @ Wo^T + bias -> outp fp32
// ---------------------------------------------------------------------------
static constexpr int PROJ_SMEM = 2 * 4 * 128 * 80;   // 81920

__global__ __launch_bounds__(256, 2) void proj_mma(const float* __restrict__ bias,
                                                   float* __restrict__ outp,
                                                   int mode)
{
    extern __shared__ __align__(16) char sm[];
    uint32_t sb = s2u(sm);
    const int tid = threadIdx.x, lane = tid & 31, w = tid >> 5;
    const int wm = w >> 2, wn = w & 3;
    const int m0 = blockIdx.y * 128, n0 = blockIdx.x * 128;
    const int lr = lane >> 2, lk = lane & 3, lc2 = (lane & 3) * 2;

    const int z = (mode == 0) ? blockIdx.z : 3;
    const size_t xoff = (mode == 0) ? (size_t)z * R_ * D_ : 0;
    const __nv_bfloat16* srcs[4] = { g_Xhi + xoff, g_Xlo + xoff,
                                     g_Whi + (size_t)z * D_ * D_,
                                     g_Wlo + (size_t)z * D_ * D_ };

    float acc[16][4];
#pragma unroll
    for (int i = 0; i < 16; ++i)
#pragma unroll
        for (int j = 0; j < 4; ++j) acc[i][j] = 0.f;

    auto prefetch = [&](int c) {
        int k0 = c * 32;
        uint32_t bufb = sb + (uint32_t)(c & 1) * 40960;
#pragma unroll
        for (int i = 0; i < 8; ++i) {
            int g = tid + i * 256;
            int t = g >> 9, idx = g & 511;
            int row = idx >> 2, gc = idx & 3;
            int grow = ((t < 2) ? m0 : n0) + row;
            uint32_t dst = bufb + (uint32_t)t * 10240 + row * 80 + gc * 16;
            cp16(dst, srcs[t] + (size_t)grow * D_ + k0 + gc * 8);
        }
        cp_commit();
    };

    prefetch(0);
    for (int c = 0; c < 32; ++c) {
        if (c + 1 < 32) { prefetch(c + 1); cp_wait1(); }
        else            { cp_wait0(); }
        __syncthreads();
        const uint32_t* XH = (const uint32_t*)(sm + (c & 1) * 40960);
        const uint32_t* XL = XH + 2560;
        const uint32_t* WH = XH + 5120;
        const uint32_t* WL = XH + 7680;
#pragma unroll
        for (int s = 0; s < 2; ++s) {
            uint32_t ah[4][4], al[4][4], bh[4][2], bl[4][2];
#pragma unroll
            for (int mt = 0; mt < 4; ++mt) {
                int r = wm * 64 + mt * 16 + lr;
                int w0 = r * 20 + s * 8 + lk, w1 = (r + 8) * 20 + s * 8 + lk;
                ah[mt][0] = XH[w0]; ah[mt][1] = XH[w1];
                ah[mt][2] = XH[w0 + 4]; ah[mt][3] = XH[w1 + 4];
                al[mt][0] = XL[w0]; al[mt][1] = XL[w1];
                al[mt][2] = XL[w0 + 4]; al[mt][3] = XL[w1 + 4];
            }
#pragma unroll
            for (int nt = 0; nt < 4; ++nt) {
                int cc = wn * 32 + nt * 8 + lr;
                int wv = cc * 20 + s * 8 + lk;
                bh[nt][0] = WH[wv]; bh[nt][1] = WH[wv + 4];
                bl[nt][0] = WL[wv]; bl[nt][1] = WL[wv + 4];
            }
            // term-outer ordering: break same-accumulator dependency chains
#pragma unroll
            for (int mt = 0; mt < 4; ++mt)
#pragma unroll
                for (int nt = 0; nt < 4; ++nt)
                    mma_bf16(acc[mt * 4 + nt], ah[mt], bh[nt]);
#pragma unroll
            for (int mt = 0; mt < 4; ++mt)
#pragma unroll
                for (int nt = 0; nt < 4; ++nt)
                    mma_bf16(acc[mt * 4 + nt], ah[mt], bl[nt]);
#pragma unroll
            for (int mt = 0; mt < 4; ++mt)
#pragma unroll
                for (int nt = 0; nt < 4; ++nt)
                    mma_bf16(acc[mt * 4 + nt], al[mt], bh[nt]);
        }
        __syncthreads();
    }

    // ---- epilogue ----
    if (mode == 3) {
#pragma unroll
        for (int mt = 0; mt < 4; ++mt)
#pragma unroll
            for (int nt = 0; nt < 4; ++nt) {
                int col = n0 + wn * 32 + nt * 8 + lc2;
                float b0 = bias[col], b1 = bias[col + 1];
                const float* a = acc[mt * 4 + nt];
#pragma unroll
                for (int hf = 0; hf < 2; ++hf) {
                    int r = m0 + wm * 64 + mt * 16 + lr + hf * 8;
                    float2 v;
                    v.x = a[hf * 2 + 0] + b0;
                    v.y = a[hf * 2 + 1] + b1;
                    *(float2*)&outp[(size_t)r * D_ + col] = v;
                }
            }
    } else if (z <= 1) {   // Q or K
        const float scl = (z == 0) ? 0.125f : 1.0f;
        __nv_bfloat16* Chi = z ? g_Khi : g_Qhi;
        __nv_bfloat16* Clo = z ? g_Klo : g_Qlo;
#pragma unroll
        for (int mt = 0; mt < 4; ++mt)
#pragma unroll
            for (int nt = 0; nt < 4; ++nt) {
                int col = n0 + wn * 32 + nt * 8 + lc2;
                int h = col >> 6, d = col & 63;
                const float* a = acc[mt * 4 + nt];
#pragma unroll
                for (int hf = 0; hf < 2; ++hf) {
                    int r = m0 + wm * 64 + mt * 16 + lr + hf * 8;
                    int ss = r >> 1, bb = r & 1;
                    float v0 = a[hf * 2 + 0] * scl;
                    float v1 = a[hf * 2 + 1] * scl;
                    __nv_bfloat16 h0, h1, l0, l1;
                    bsplit(v0, h0, l0); bsplit(v1, h1, l1);
                    size_t o = (((size_t)(bb * H_ + h)) * S_ + ss) * DK_ + d;
                    *(__nv_bfloat162*)&Chi[o] = bf2(h0, h1);
                    *(__nv_bfloat162*)&Clo[o] = bf2(l0, l1);
                }
            }
    } else {  // z == 2: V -> transposed g_Vt (stage fp32 in smem, scatter)
        float* sD = (float*)sm;   // 128 x 132
#pragma unroll
        for (int mt = 0; mt < 4; ++mt)
#pragma unroll
            for (int nt = 0; nt < 4; ++nt) {
                int col = wn * 32 + nt * 8 + lc2;
                const float* a = acc[mt * 4 + nt];
#pragma unroll
                for (int hf = 0; hf < 2; ++hf) {
                    int r = wm * 64 + mt * 16 + lr + hf * 8;
                    float2 v = make_float2(a[hf * 2 + 0], a[hf * 2 + 1]);
                    *(float2*)&sD[r * 132 + col] = v;
                }
            }
        __syncthreads();
        for (int e = tid; e < 16384; e += 256) {
            int row = e & 127, col = e >> 7;
            float v = sD[row * 132 + col];
            int tok = m0 + row;
            int ss = tok >> 1, bb = tok & 1;
            int gc = n0 + col;
            int h = gc >> 6, d = gc & 63;
            __nv_bfloat16 hh, ll;
            bsplit(v, hh, ll);
            size_t o = ((size_t)(bb * H_ + h) * DK_ + d) * S_ + ss;
            g_Vthi[o] = hh;
            g_Vtlo[o] = ll;
        }
    }
}

// ---------------------------------------------------------------------------
// scores_mma: per z, 128(q) x 128(k) tile of Q.K^T (K=64), masks, -> attn raw,
// plus per-tile row max / exp-sum partials for softmax stats.
// ---------------------------------------------------------------------------
static constexpr int SC_SMEM = 4 * 128 * 144;        // 73728

__global__ __launch_bounds__(256, 2) void scores_mma(float* __restrict__ attn_g)
{
    extern __shared__ __align__(16) char sm[];
    uint32_t sb = s2u(sm);
    const int tid = threadIdx.x, lane = tid & 31, w = tid >> 5;
    const int wm = w >> 2, wn = w & 3;
    const int n0 = blockIdx.x * 128, m0 = blockIdx.y * 128, z = blockIdx.z;
    const int b = z >> 4;
    const int lr = lane >> 2, lk = lane & 3, lc2 = (lane & 3) * 2;

    const size_t zoff = (size_t)z * S_ * DK_;
    const __nv_bfloat16* srcs[4] = { g_Qhi + zoff, g_Qlo + zoff,
                                     g_Khi + zoff, g_Klo + zoff };
#pragma unroll
    for (int i = 0; i < 16; ++i) {
        int g = tid + i * 256;
        int t = g >> 10, idx = g & 1023;
        int row = idx >> 3, gc = idx & 7;
        int grow = ((t < 2) ? m0 : n0) + row;
        uint32_t dst = sb + (uint32_t)t * 18432 + row * 144 + gc * 16;
        cp16(dst, srcs[t] + (size_t)grow * DK_ + gc * 8);
    }
    cp_commit();
    cp_wait0();
    __syncthreads();

    float acc[16][4];
#pragma unroll
    for (int i = 0; i < 16; ++i)
#pragma unroll
        for (int j = 0; j < 4; ++j) acc[i][j] = 0.f;

    const uint32_t* QH = (const uint32_t*)sm;
    const uint32_t* QL = QH + 4608;
    const uint32_t* KH = QH + 9216;
    const uint32_t* KL = QH + 13824;

#pragma unroll
    for (int s = 0; s < 4; ++s) {
        uint32_t ah[4][4], al[4][4], bh[4][2], bl[4][2];
#pragma unroll
        for (int mt = 0; mt < 4; ++mt) {
            int r = wm * 64 + mt * 16 + lr;
            int w0 = r * 36 + s * 8 + lk, w1 = (r + 8) * 36 + s * 8 + lk;
            ah[mt][0] = QH[w0]; ah[mt][1] = QH[w1];
            ah[mt][2] = QH[w0 + 4]; ah[mt][3] = QH[w1 + 4];
            al[mt][0] = QL[w0]; al[mt][1] = QL[w1];
            al[mt][2] = QL[w0 + 4]; al[mt][3] = QL[w1 + 4];
        }
#pragma unroll
        for (int nt = 0; nt < 4; ++nt) {
            int cc = wn * 32 + nt * 8 + lr;
            int wv = cc * 36 + s * 8 + lk;
            bh[nt][0] = KH[wv]; bh[nt][1] = KH[wv + 4];
            bl[nt][0] = KL[wv]; bl[nt][1] = KL[wv + 4];
        }
#pragma unroll
        for (int mt = 0; mt < 4; ++mt)
#pragma unroll
            for (int nt = 0; nt < 4; ++nt)
                mma_bf16(acc[mt * 4 + nt], ah[mt], bh[nt]);
#pragma unroll
        for (int mt = 0; mt < 4; ++mt)
#pragma unroll
            for (int nt = 0; nt < 4; ++nt)
                mma_bf16(acc[mt * 4 + nt], ah[mt], bl[nt]);
#pragma unroll
        for (int mt = 0; mt < 4; ++mt)
#pragma unroll
            for (int nt = 0; nt < 4; ++nt)
                mma_bf16(acc[mt * 4 + nt], al[mt], bh[nt]);
    }
    __syncthreads();

    // stage to smem, then masked coalesced store + per-tile row stats
    float* sD = (float*)sm;   // 128 x 132
#pragma unroll
    for (int mt = 0; mt < 4; ++mt)
#pragma unroll
        for (int nt = 0; nt < 4; ++nt) {
            int col = wn * 32 + nt * 8 + lc2;
            const float* a = acc[mt * 4 + nt];
#pragma unroll
            for (int hf = 0; hf < 2; ++hf) {
                int r = wm * 64 + mt * 16 + lr + hf * 8;
                *(float2*)&sD[r * 132 + col] = make_float2(a[hf * 2], a[hf * 2 + 1]);
            }
        }
    __syncthreads();

    const unsigned char* cmb = g_cmb + (size_t)b * S_ * S_;
    float* ap = attn_g + (size_t)z * S_ * S_;
    const int kt = blockIdx.x;           // k-tile index 0..15
#pragma unroll
    for (int i = 0; i < 16; ++i) {
        int e = tid + i * 256;
        int row = e >> 5;                // whole warp on one row
        int c4 = (e & 31) * 4;
        int q = m0 + row, k = n0 + c4;
        float4 v = *(float4*)&sD[row * 132 + c4];
        uchar4 f = *(const uchar4*)&cmb[(size_t)q * S_ + k];
        if (f.x) v.x = -1.0e9f;
        if (f.y) v.y = -1.0e9f;
        if (f.z) v.z = -1.0e9f;
        if (f.w) v.w = -1.0e9f;
        *(float4*)&ap[(size_t)q * S_ + k] = v;
        // warp-level row stats (row == whole warp)
        float m4 = fmaxf(fmaxf(v.x, v.y), fmaxf(v.z, v.w));
#pragma unroll
        for (int o = 16; o; o >>= 1)
            m4 = fmaxf(m4, __shfl_xor_sync(0xffffffffu, m4, o));
        float s4 = __expf(v.x - m4) + __expf(v.y - m4) +
                   __expf(v.z - m4) + __expf(v.w - m4);
#pragma unroll
        for (int o = 16; o; o >>= 1)
            s4 += __shfl_xor_sync(0xffffffffu, s4, o);
        if (lane == 0) {
            size_t idx = ((size_t)z * S_ + q) * 16 + kt;
            g_pm[idx] = m4;
            g_ps[idx] = s4;
        }
    }
}

// ---------------------------------------------------------------------------
// combine_kernel: reduce 16 per-tile partials per row -> g_mx, g_inv
// ---------------------------------------------------------------------------
__global__ __launch_bounds__(256) void combine_kernel()
{
    size_t row = (size_t)blockIdx.x * 256 + threadIdx.x;   // Z_*S_ rows
    const float* pm = g_pm + row * 16;
    const float* ps = g_ps + row * 16;
    float gm = pm[0];
#pragma unroll
    for (int t = 1; t < 16; ++t) gm = fmaxf(gm, pm[t]);
    float s = 0.f;
#pragma unroll
    for (int t = 0; t < 16; ++t) s += ps[t] * __expf(pm[t] - gm);
    g_mx[row]  = gm;
    g_inv[row] = 1.0f / s;
}

// ---------------------------------------------------------------------------
// av_mma: per z, ctx[64(q) x 64(d)] = softmax(raw) @ V, K=2048 chunks of 64.
// Reads raw scores, computes p = exp(s-mx)*inv in registers, writes p back
// to attn (final output), converts p to bf16 hi/lo for mma.
// ---------------------------------------------------------------------------
static constexpr int AV_STG0 = 0;
static constexpr int AV_VT0  = 2 * 17408;                  // 34816
static constexpr int AV_AH   = AV_VT0 + 2 * 18432;         // 71680
static constexpr int AV_AL   = AV_AH + 9216;               // 80896
static constexpr int AV_SMEM = AV_AL + 9216;               // 90112

__global__ __launch_bounds__(256, 2) void av_mma(float* __restrict__ attn_g)
{
    extern __shared__ __align__(16) char sm[];
    uint32_t sb = s2u(sm);
    const int tid = threadIdx.x, lane = tid & 31, w = tid >> 5;
    const int wm = w >> 1, wn = w & 1;
    const int m0 = blockIdx.x * 64, z = blockIdx.y;
    const int lr = lane >> 2, lk = lane & 3, lc2 = (lane & 3) * 2;

    float* Ag = attn_g + (size_t)z * S_ * S_;
    const __nv_bfloat16* Vh = g_Vthi + (size_t)z * DK_ * S_;
    const __nv_bfloat16* Vl = g_Vtlo + (size_t)z * DK_ * S_;

    float acc[4][4];
#pragma unroll
    for (int i = 0; i < 4; ++i)
#pragma unroll
        for (int j = 0; j < 4; ++j) acc[i][j] = 0.f;

    const int cr = tid >> 2;                 // 0..63
    const int cb = (tid & 3) * 16;           // 0,16,32,48
    const float smx  = g_mx [(size_t)z * S_ + m0 + cr];
    const float sinv = g_inv[(size_t)z * S_ + m0 + cr];

    auto prefetch = [&](int c) {
        int k0 = c * 64;
        int bi = c & 1;
#pragma unroll
        for (int i = 0; i < 8; ++i) {
            int g = tid + i * 256;
            if (g < 1024) {
                int row = g >> 4, c16 = g & 15;
                uint32_t dst = sb + AV_STG0 + (uint32_t)bi * 17408 + row * 272 + c16 * 16;
                cp16(dst, Ag + (size_t)(m0 + row) * S_ + k0 + c16 * 4);
            } else {
                int g2 = g - 1024;
                int t = g2 >> 9, idx = g2 & 511;
                int row = idx >> 3, gc = idx & 7;
                uint32_t dst = sb + AV_VT0 + (uint32_t)bi * 18432 + (uint32_t)t * 9216 +
                               row * 144 + gc * 16;
                cp16(dst, (t ? Vl : Vh) + (size_t)row * S_ + k0 + gc * 8);
            }
        }
        cp_commit();
    };

    prefetch(0);
    for (int c = 0; c < 32; ++c) {
        if (c + 1 < 32) { prefetch(c + 1); cp_wait1(); }
        else            { cp_wait0(); }
        __syncthreads();
        // conversion: raw -> p, write p to gmem, split to bf16 hi/lo
        {
            const int k0 = c * 64;
            const float* st = (const float*)(sm + AV_STG0 + (c & 1) * 17408);
            uint32_t* AH = (uint32_t*)(sm + AV_AH);
            uint32_t* AL = (uint32_t*)(sm + AV_AL);
            float* prow = Ag + (size_t)(m0 + cr) * S_ + k0;
#pragma unroll
            for (int c4 = 0; c4 < 16; c4 += 4) {
                float4 v = *(const float4*)&st[cr * 68 + cb + c4];
                float4 p;
                p.x = __expf(v.x - smx) * sinv;
                p.y = __expf(v.y - smx) * sinv;
                p.z = __expf(v.z - smx) * sinv;
                p.w = __expf(v.w - smx) * sinv;
                *(float4*)&prow[cb + c4] = p;
                __nv_bfloat16 h0, h1, h2, h3, l0, l1, l2, l3;
                bsplit(p.x, h0, l0); bsplit(p.y, h1, l1);
                bsplit(p.z, h2, l2); bsplit(p.w, h3, l3);
                int wbase = cr * 36 + (cb + c4) / 2;
                AH[wbase]     = pack2(h0, h1);
                AH[wbase + 1] = pack2(h2, h3);
                AL[wbase]     = pack2(l0, l1);
                AL[wbase + 1] = pack2(l2, l3);
            }
        }
        __syncthreads();

        const uint32_t* AH = (const uint32_t*)(sm + AV_AH);
        const uint32_t* AL = (const uint32_t*)(sm + AV_AL);
        const uint32_t* VH = (const uint32_t*)(sm + AV_VT0 + (c & 1) * 18432);
        const uint32_t* VL = VH + 2304;
#pragma unroll
        for (int s = 0; s < 4; ++s) {
            uint32_t ah[4], al[4], bh[4][2], bl[4][2];
            {
                int r = wm * 16 + lr;
                int w0 = r * 36 + s * 8 + lk, w1 = (r + 8) * 36 + s * 8 + lk;
                ah[0] = AH[w0]; ah[1] = AH[w1];
                ah[2] = AH[w0 + 4]; ah[3] = AH[w1 + 4];
                al[0] = AL[w0]; al[1] = AL[w1];
                al[2] = AL[w0 + 4]; al[3] = AL[w1 + 4];
            }
#pragma unroll
            for (int nt = 0; nt < 4; ++nt) {
                int cc = wn * 32 + nt * 8 + lr;
                int wv = cc * 36 + s * 8 + lk;
                bh[nt][0] = VH[wv]; bh[nt][1] = VH[wv + 4];
                bl[nt][0] = VL[wv]; bl[nt][1] = VL[wv + 4];
            }
#pragma unroll
            for (int nt = 0; nt < 4; ++nt)
                mma_bf16(acc[nt], ah, bh[nt]);
#pragma unroll
            for (int nt = 0; nt < 4; ++nt)
                mma_bf16(acc[nt], ah, bl[nt]);
#pragma unroll
            for (int nt = 0; nt < 4; ++nt)
                mma_bf16(acc[nt], al, bh[nt]);
        }
        __syncthreads();
    }

    // epilogue: split ctx -> g_Xhi/g_Xlo slot 0 in (S,B,D) token layout
    const int bb = z >> 4, h = z & 15;
#pragma unroll
    for (int nt = 0; nt < 4; ++nt) {
        int d = wn * 32 + nt * 8 + lc2;
        const float* a = acc[nt];
#pragma unroll
        for (int hf = 0; hf < 2; ++hf) {
            int q = m0 + wm * 16 + lr + hf * 8;
            size_t o = ((size_t)q * B_ + bb) * D_ + h * DK_ + d;
            __nv_bfloat16 h0, h1, l0, l1;
            bsplit(a[hf * 2 + 0], h0, l0);
            bsplit(a[hf * 2 + 1], h1, l1);
            *(__nv_bfloat162*)&g_Xhi[o] = bf2(h0, h1);
            *(__nv_bfloat162*)&g_Xlo[o] = bf2(l0, l1);
        }
    }
}

// ---------------------------------------------------------------------------
extern "C" void kernel_launch(void* const* d_in, const int* in_sizes, int n_in,
                              void* d_out, int out_size)
{
    (void)in_sizes; (void)n_in; (void)out_size;
    const float* query = (const float*)d_in[0];
    const float* key   = (const float*)d_in[1];
    const float* value = (const float*)d_in[2];
    const int*   mask  = (const int*)d_in[3];
    const int*   kpm   = (const int*)d_in[4];
    const float* Wq    = (const float*)d_in[5];
    const float* Wk    = (const float*)d_in[6];
    const float* Wv    = (const float*)d_in[7];
    const float* Wo    = (const float*)d_in[8];
    const float* bo    = (const float*)d_in[9];

    float* out  = (float*)d_out;
    float* attn = out + (size_t)S_ * B_ * D_;   // tuple: (out, attn)

    cudaFuncSetAttribute(proj_mma,   cudaFuncAttributeMaxDynamicSharedMemorySize, PROJ_SMEM);
    cudaFuncSetAttribute(scores_mma, cudaFuncAttributeMaxDynamicSharedMemorySize, SC_SMEM);
    cudaFuncSetAttribute(av_mma,     cudaFuncAttributeMaxDynamicSharedMemorySize, AV_SMEM);

    mask_cmb<<<dim3(S_ * S_ / 1024, B_), 256>>>(mask, kpm);
    conv_split_x<<<dim3(R_ * D_ / 1024, 3), 256>>>(query, key, value);
    conv_split_w<<<dim3(D_ * D_ / 1024, 4), 256>>>(Wq, Wk, Wv, Wo);

    proj_mma<<<dim3(D_ / 128, R_ / 128, 3), 256, PROJ_SMEM>>>(nullptr, nullptr, 0);

    scores_mma<<<dim3(S_ / 128, S_ / 128, Z_), 256, SC_SMEM>>>(attn);
    combine_kernel<<<Z_ * S_ / 256, 256>>>();
    av_mma<<<dim3(S_ / 64, Z_), 256, AV_SMEM>>>(attn);

    proj_mma<<<dim3(D_ / 128, R_ / 128, 1), 256, PROJ_SMEM>>>(bo, out, 3);
}

// round 13
// speedup vs baseline: 1.9629x; 1.0288x over previous
#include <cuda_runtime.h>
#include <cuda_bf16.h>
#include <cstdint>

static constexpr int S_  = 2048;
static constexpr int B_  = 2;
static constexpr int D_  = 1024;
static constexpr int H_  = 16;
static constexpr int DK_ = 64;
static constexpr int R_  = S_ * B_;     // 4096 token rows
static constexpr int Z_  = B_ * H_;     // 32 (b,h) planes

// ---------------------------------------------------------------------------
// Device-global scratch.  X slots: 0=query/ctx, 1=key, 2=value.  W slots:
// 0=Wq, 1=Wk, 2=Wv, 3=Wo.
// ---------------------------------------------------------------------------
__device__ __nv_bfloat16 g_Xhi[(size_t)3 * R_ * D_];
__device__ __nv_bfloat16 g_Xlo[(size_t)3 * R_ * D_];
__device__ __nv_bfloat16 g_Whi[(size_t)4 * D_ * D_];
__device__ __nv_bfloat16 g_Wlo[(size_t)4 * D_ * D_];
__device__ __nv_bfloat16 g_Qhi[(size_t)Z_ * S_ * DK_];
__device__ __nv_bfloat16 g_Qlo[(size_t)Z_ * S_ * DK_];
__device__ __nv_bfloat16 g_Khi[(size_t)Z_ * S_ * DK_];
__device__ __nv_bfloat16 g_Klo[(size_t)Z_ * S_ * DK_];
__device__ __nv_bfloat16 g_Vthi[(size_t)Z_ * DK_ * S_];   // (z, d, s)
__device__ __nv_bfloat16 g_Vtlo[(size_t)Z_ * DK_ * S_];
__device__ unsigned char g_cmb[(size_t)B_ * S_ * S_];     // 1 = masked
__device__ float g_pm[(size_t)Z_ * S_ * 16];              // per-tile row max
__device__ float g_ps[(size_t)Z_ * S_ * 16];              // per-tile exp-sum

// ---------------------------------------------------------------------------
// helpers
// ---------------------------------------------------------------------------
__device__ __forceinline__ uint32_t s2u(const void* p) {
    uint32_t a;
    asm("{ .reg .u64 t; cvta.to.shared.u64 t, %1; cvt.u32.u64 %0, t; }"
        : "=r"(a) : "l"(p));
    return a;
}
__device__ __forceinline__ void cp16(uint32_t d, const void* s) {
    asm volatile(
        "{ .reg .u64 g; cvta.to.global.u64 g, %1; "
        "cp.async.cg.shared.global [%0], [g], 16; }"
        :: "r"(d), "l"(s));
}
__device__ __forceinline__ void cp_commit() {
    asm volatile("cp.async.commit_group;" ::: "memory");
}
__device__ __forceinline__ void cp_wait0() {
    asm volatile("cp.async.wait_group 0;" ::: "memory");
}
__device__ __forceinline__ void cp_wait1() {
    asm volatile("cp.async.wait_group 1;" ::: "memory");
}

__device__ __forceinline__ void mma_bf16(float* c, const uint32_t* a, const uint32_t* b)
{
    asm volatile(
        "mma.sync.aligned.m16n8k16.row.col.f32.bf16.bf16.f32 "
        "{%0,%1,%2,%3}, {%4,%5,%6,%7}, {%8,%9}, {%0,%1,%2,%3};"
        : "+f"(c[0]), "+f"(c[1]), "+f"(c[2]), "+f"(c[3])
        : "r"(a[0]), "r"(a[1]), "r"(a[2]), "r"(a[3]), "r"(b[0]), "r"(b[1]));
}

__device__ __forceinline__ void bsplit(float v, __nv_bfloat16& h, __nv_bfloat16& l) {
    h = __float2bfloat16(v);
    l = __float2bfloat16(v - __bfloat162float(h));
}
__device__ __forceinline__ __nv_bfloat162 bf2(__nv_bfloat16 a, __nv_bfloat16 b) {
    __nv_bfloat162 t; t.x = a; t.y = b; return t;
}
__device__ __forceinline__ uint32_t pack2(__nv_bfloat16 a, __nv_bfloat16 b) {
    return (uint32_t)__bfloat16_as_ushort(a) |
           ((uint32_t)__bfloat16_as_ushort(b) << 16);
}

// ---------------------------------------------------------------------------
// fp32 -> bf16 hi/lo splits (slotted)
// ---------------------------------------------------------------------------
__global__ __launch_bounds__(256) void conv_split_x(const float* __restrict__ q,
                                                    const float* __restrict__ k,
                                                    const float* __restrict__ v)
{
    const int z = blockIdx.y;
    const float* src = (z == 0) ? q : (z == 1) ? k : v;
    __nv_bfloat16* hi = g_Xhi + (size_t)z * R_ * D_;
    __nv_bfloat16* lo = g_Xlo + (size_t)z * R_ * D_;
    int i = blockIdx.x * 256 + threadIdx.x;   // over R*D/4
    float4 val = ((const float4*)src)[i];
    __nv_bfloat16 h0, h1, h2, h3, l0, l1, l2, l3;
    bsplit(val.x, h0, l0); bsplit(val.y, h1, l1);
    bsplit(val.z, h2, l2); bsplit(val.w, h3, l3);
    ((__nv_bfloat162*)hi)[i * 2]     = bf2(h0, h1);
    ((__nv_bfloat162*)hi)[i * 2 + 1] = bf2(h2, h3);
    ((__nv_bfloat162*)lo)[i * 2]     = bf2(l0, l1);
    ((__nv_bfloat162*)lo)[i * 2 + 1] = bf2(l2, l3);
}

__global__ __launch_bounds__(256) void conv_split_w(const float* __restrict__ wq,
                                                    const float* __restrict__ wk,
                                                    const float* __restrict__ wv,
                                                    const float* __restrict__ wo)
{
    const int z = blockIdx.y;
    const float* src = (z == 0) ? wq : (z == 1) ? wk : (z == 2) ? wv : wo;
    __nv_bfloat16* hi = g_Whi + (size_t)z * D_ * D_;
    __nv_bfloat16* lo = g_Wlo + (size_t)z * D_ * D_;
    int i = blockIdx.x * 256 + threadIdx.x;   // over D*D/4
    float4 val = ((const float4*)src)[i];
    __nv_bfloat16 h0, h1, h2, h3, l0, l1, l2, l3;
    bsplit(val.x, h0, l0); bsplit(val.y, h1, l1);
    bsplit(val.z, h2, l2); bsplit(val.w, h3, l3);
    ((__nv_bfloat162*)hi)[i * 2]     = bf2(h0, h1);
    ((__nv_bfloat162*)hi)[i * 2 + 1] = bf2(h2, h3);
    ((__nv_bfloat162*)lo)[i * 2]     = bf2(l0, l1);
    ((__nv_bfloat162*)lo)[i * 2 + 1] = bf2(l2, l3);
}

// combined mask flags: cmb[b][q][k] = (mask==0 || kpm==0)
__global__ __launch_bounds__(256) void mask_cmb(const int* __restrict__ mask,
                                                const int* __restrict__ kpm)
{
    int b = blockIdx.y;
    size_t i = (size_t)blockIdx.x * 256 + threadIdx.x;   // per uchar4
    int q  = (int)(i >> 9);
    int k4 = (int)(i & 511) << 2;
    int4 m  = *(const int4*)&mask[(size_t)q * S_ + k4];
    int4 kp = *(const int4*)&kpm[(size_t)b * S_ + k4];
    uchar4 r;
    r.x = (m.x == 0 || kp.x == 0); r.y = (m.y == 0 || kp.y == 0);
    r.z = (m.z == 0 || kp.z == 0); r.w = (m.w == 0 || kp.w == 0);
    *(uchar4*)&g_cmb[((size_t)b * S_ + q) * S_ + k4] = r;
}

// ---------------------------------------------------------------------------
// proj_mma: C[4096,1024] = X @ W^T, tile 128x128, BK=32, warps 2(m)x4(n).
//  mode 0: batched QKV (blockIdx.z selects slot; epilogue per slot)
//  mode 3: ctx (X slot 0) @ Wo^T + bias -> outp fp32
// ---------------------------------------------------------------------------
static constexpr int PROJ_SMEM = 2 * 4 * 128 * 80;   // 81920

__global__ __launch_bounds__(256, 2) void proj_mma(const float* __restrict__ bias,
                                                   float* __restrict__ outp,
                                                   int mode)
{
    extern __shared__ __align__(16) char sm[];
    uint32_t sb = s2u(sm);
    const int tid = threadIdx.x, lane = tid & 31, w = tid >> 5;
    const int wm = w >> 2, wn = w & 3;
    const int m0 = blockIdx.y * 128, n0 = blockIdx.x * 128;
    const int lr = lane >> 2, lk = lane & 3, lc2 = (lane & 3) * 2;

    const int z = (mode == 0) ? blockIdx.z : 3;
    const size_t xoff = (mode == 0) ? (size_t)z * R_ * D_ : 0;
    const __nv_bfloat16* srcs[4] = { g_Xhi + xoff, g_Xlo + xoff,
                                     g_Whi + (size_t)z * D_ * D_,
                                     g_Wlo + (size_t)z * D_ * D_ };

    float acc[16][4];
#pragma unroll
    for (int i = 0; i < 16; ++i)
#pragma unroll
        for (int j = 0; j < 4; ++j) acc[i][j] = 0.f;

    auto prefetch = [&](int c) {
        int k0 = c * 32;
        uint32_t bufb = sb + (uint32_t)(c & 1) * 40960;
#pragma unroll
        for (int i = 0; i < 8; ++i) {
            int g = tid + i * 256;
            int t = g >> 9, idx = g & 511;
            int row = idx >> 2, gc = idx & 3;
            int grow = ((t < 2) ? m0 : n0) + row;
            uint32_t dst = bufb + (uint32_t)t * 10240 + row * 80 + gc * 16;
            cp16(dst, srcs[t] + (size_t)grow * D_ + k0 + gc * 8);
        }
        cp_commit();
    };

    prefetch(0);
    for (int c = 0; c < 32; ++c) {
        if (c + 1 < 32) { prefetch(c + 1); cp_wait1(); }
        else            { cp_wait0(); }
        __syncthreads();
        const uint32_t* XH = (const uint32_t*)(sm + (c & 1) * 40960);
        const uint32_t* XL = XH + 2560;
        const uint32_t* WH = XH + 5120;
        const uint32_t* WL = XH + 7680;
#pragma unroll
        for (int s = 0; s < 2; ++s) {
            uint32_t ah[4][4], al[4][4], bh[4][2], bl[4][2];
#pragma unroll
            for (int mt = 0; mt < 4; ++mt) {
                int r = wm * 64 + mt * 16 + lr;
                int w0 = r * 20 + s * 8 + lk, w1 = (r + 8) * 20 + s * 8 + lk;
                ah[mt][0] = XH[w0]; ah[mt][1] = XH[w1];
                ah[mt][2] = XH[w0 + 4]; ah[mt][3] = XH[w1 + 4];
                al[mt][0] = XL[w0]; al[mt][1] = XL[w1];
                al[mt][2] = XL[w0 + 4]; al[mt][3] = XL[w1 + 4];
            }
#pragma unroll
            for (int nt = 0; nt < 4; ++nt) {
                int cc = wn * 32 + nt * 8 + lr;
                int wv = cc * 20 + s * 8 + lk;
                bh[nt][0] = WH[wv]; bh[nt][1] = WH[wv + 4];
                bl[nt][0] = WL[wv]; bl[nt][1] = WL[wv + 4];
            }
            // term-outer ordering: break same-accumulator dependency chains
#pragma unroll
            for (int mt = 0; mt < 4; ++mt)
#pragma unroll
                for (int nt = 0; nt < 4; ++nt)
                    mma_bf16(acc[mt * 4 + nt], ah[mt], bh[nt]);
#pragma unroll
            for (int mt = 0; mt < 4; ++mt)
#pragma unroll
                for (int nt = 0; nt < 4; ++nt)
                    mma_bf16(acc[mt * 4 + nt], ah[mt], bl[nt]);
#pragma unroll
            for (int mt = 0; mt < 4; ++mt)
#pragma unroll
                for (int nt = 0; nt < 4; ++nt)
                    mma_bf16(acc[mt * 4 + nt], al[mt], bh[nt]);
        }
        __syncthreads();
    }

    // ---- epilogue ----
    if (mode == 3) {
#pragma unroll
        for (int mt = 0; mt < 4; ++mt)
#pragma unroll
            for (int nt = 0; nt < 4; ++nt) {
                int col = n0 + wn * 32 + nt * 8 + lc2;
                float b0 = bias[col], b1 = bias[col + 1];
                const float* a = acc[mt * 4 + nt];
#pragma unroll
                for (int hf = 0; hf < 2; ++hf) {
                    int r = m0 + wm * 64 + mt * 16 + lr + hf * 8;
                    float2 v;
                    v.x = a[hf * 2 + 0] + b0;
                    v.y = a[hf * 2 + 1] + b1;
                    *(float2*)&outp[(size_t)r * D_ + col] = v;
                }
            }
    } else if (z <= 1) {   // Q or K
        const float scl = (z == 0) ? 0.125f : 1.0f;
        __nv_bfloat16* Chi = z ? g_Khi : g_Qhi;
        __nv_bfloat16* Clo = z ? g_Klo : g_Qlo;
#pragma unroll
        for (int mt = 0; mt < 4; ++mt)
#pragma unroll
            for (int nt = 0; nt < 4; ++nt) {
                int col = n0 + wn * 32 + nt * 8 + lc2;
                int h = col >> 6, d = col & 63;
                const float* a = acc[mt * 4 + nt];
#pragma unroll
                for (int hf = 0; hf < 2; ++hf) {
                    int r = m0 + wm * 64 + mt * 16 + lr + hf * 8;
                    int ss = r >> 1, bb = r & 1;
                    float v0 = a[hf * 2 + 0] * scl;
                    float v1 = a[hf * 2 + 1] * scl;
                    __nv_bfloat16 h0, h1, l0, l1;
                    bsplit(v0, h0, l0); bsplit(v1, h1, l1);
                    size_t o = (((size_t)(bb * H_ + h)) * S_ + ss) * DK_ + d;
                    *(__nv_bfloat162*)&Chi[o] = bf2(h0, h1);
                    *(__nv_bfloat162*)&Clo[o] = bf2(l0, l1);
                }
            }
    } else {  // z == 2: V -> transposed g_Vt (stage fp32 in smem, scatter)
        float* sD = (float*)sm;   // 128 x 132
#pragma unroll
        for (int mt = 0; mt < 4; ++mt)
#pragma unroll
            for (int nt = 0; nt < 4; ++nt) {
                int col = wn * 32 + nt * 8 + lc2;
                const float* a = acc[mt * 4 + nt];
#pragma unroll
                for (int hf = 0; hf < 2; ++hf) {
                    int r = wm * 64 + mt * 16 + lr + hf * 8;
                    float2 v = make_float2(a[hf * 2 + 0], a[hf * 2 + 1]);
                    *(float2*)&sD[r * 132 + col] = v;
                }
            }
        __syncthreads();
        for (int e = tid; e < 16384; e += 256) {
            int row = e & 127, col = e >> 7;
            float v = sD[row * 132 + col];
            int tok = m0 + row;
            int ss = tok >> 1, bb = tok & 1;
            int gc = n0 + col;
            int h = gc >> 6, d = gc & 63;
            __nv_bfloat16 hh, ll;
            bsplit(v, hh, ll);
            size_t o = ((size_t)(bb * H_ + h) * DK_ + d) * S_ + ss;
            g_Vthi[o] = hh;
            g_Vtlo[o] = ll;
        }
    }
}

// ---------------------------------------------------------------------------
// scores_mma: per z, 128(q) x 128(k) tile of Q.K^T (K=64), masks.
// Stores e_t = exp(s - m_tile) into attn, plus per-tile row max / exp-sum.
// ---------------------------------------------------------------------------
static constexpr int SC_SMEM = 4 * 128 * 144;        // 73728

__global__ __launch_bounds__(256, 2) void scores_mma(float* __restrict__ attn_g)
{
    extern __shared__ __align__(16) char sm[];
    uint32_t sb = s2u(sm);
    const int tid = threadIdx.x, lane = tid & 31, w = tid >> 5;
    const int wm = w >> 2, wn = w & 3;
    const int n0 = blockIdx.x * 128, m0 = blockIdx.y * 128;
    const int z = blockIdx.z;
    const int b = z >> 4;
    const int lr = lane >> 2, lk = lane & 3, lc2 = (lane & 3) * 2;

    const size_t zoff = (size_t)z * S_ * DK_;
    const __nv_bfloat16* srcs[4] = { g_Qhi + zoff, g_Qlo + zoff,
                                     g_Khi + zoff, g_Klo + zoff };
#pragma unroll
    for (int i = 0; i < 16; ++i) {
        int g = tid + i * 256;
        int t = g >> 10, idx = g & 1023;
        int row = idx >> 3, gc = idx & 7;
        int grow = ((t < 2) ? m0 : n0) + row;
        uint32_t dst = sb + (uint32_t)t * 18432 + row * 144 + gc * 16;
        cp16(dst, srcs[t] + (size_t)grow * DK_ + gc * 8);
    }
    cp_commit();
    cp_wait0();
    __syncthreads();

    float acc[16][4];
#pragma unroll
    for (int i = 0; i < 16; ++i)
#pragma unroll
        for (int j = 0; j < 4; ++j) acc[i][j] = 0.f;

    const uint32_t* QH = (const uint32_t*)sm;
    const uint32_t* QL = QH + 4608;
    const uint32_t* KH = QH + 9216;
    const uint32_t* KL = QH + 13824;

#pragma unroll
    for (int s = 0; s < 4; ++s) {
        uint32_t ah[4][4], al[4][4], bh[4][2], bl[4][2];
#pragma unroll
        for (int mt = 0; mt < 4; ++mt) {
            int r = wm * 64 + mt * 16 + lr;
            int w0 = r * 36 + s * 8 + lk, w1 = (r + 8) * 36 + s * 8 + lk;
            ah[mt][0] = QH[w0]; ah[mt][1] = QH[w1];
            ah[mt][2] = QH[w0 + 4]; ah[mt][3] = QH[w1 + 4];
            al[mt][0] = QL[w0]; al[mt][1] = QL[w1];
            al[mt][2] = QL[w0 + 4]; al[mt][3] = QL[w1 + 4];
        }
#pragma unroll
        for (int nt = 0; nt < 4; ++nt) {
            int cc = wn * 32 + nt * 8 + lr;
            int wv = cc * 36 + s * 8 + lk;
            bh[nt][0] = KH[wv]; bh[nt][1] = KH[wv + 4];
            bl[nt][0] = KL[wv]; bl[nt][1] = KL[wv + 4];
        }
#pragma unroll
        for (int mt = 0; mt < 4; ++mt)
#pragma unroll
            for (int nt = 0; nt < 4; ++nt)
                mma_bf16(acc[mt * 4 + nt], ah[mt], bh[nt]);
#pragma unroll
        for (int mt = 0; mt < 4; ++mt)
#pragma unroll
            for (int nt = 0; nt < 4; ++nt)
                mma_bf16(acc[mt * 4 + nt], ah[mt], bl[nt]);
#pragma unroll
        for (int mt = 0; mt < 4; ++mt)
#pragma unroll
            for (int nt = 0; nt < 4; ++nt)
                mma_bf16(acc[mt * 4 + nt], al[mt], bh[nt]);
    }
    __syncthreads();

    // stage to smem, then masked e_t store + per-tile row stats
    float* sD = (float*)sm;   // 128 x 132
#pragma unroll
    for (int mt = 0; mt < 4; ++mt)
#pragma unroll
        for (int nt = 0; nt < 4; ++nt) {
            int col = wn * 32 + nt * 8 + lc2;
            const float* a = acc[mt * 4 + nt];
#pragma unroll
            for (int hf = 0; hf < 2; ++hf) {
                int r = wm * 64 + mt * 16 + lr + hf * 8;
                *(float2*)&sD[r * 132 + col] = make_float2(a[hf * 2], a[hf * 2 + 1]);
            }
        }
    __syncthreads();

    const unsigned char* cmb = g_cmb + (size_t)b * S_ * S_;
    float* ap = attn_g + (size_t)z * S_ * S_;
    const int kt = blockIdx.x;           // k-tile index 0..15
#pragma unroll
    for (int i = 0; i < 16; ++i) {
        int e = tid + i * 256;
        int row = e >> 5;                // whole warp on one row
        int c4 = (e & 31) * 4;
        int q = m0 + row, k = n0 + c4;
        float4 v = *(float4*)&sD[row * 132 + c4];
        uchar4 f = *(const uchar4*)&cmb[(size_t)q * S_ + k];
        if (f.x) v.x = -1.0e9f;
        if (f.y) v.y = -1.0e9f;
        if (f.z) v.z = -1.0e9f;
        if (f.w) v.w = -1.0e9f;
        // warp-level row max (row == whole warp)
        float m4 = fmaxf(fmaxf(v.x, v.y), fmaxf(v.z, v.w));
#pragma unroll
        for (int o = 16; o; o >>= 1)
            m4 = fmaxf(m4, __shfl_xor_sync(0xffffffffu, m4, o));
        float4 ee;
        ee.x = __expf(v.x - m4);
        ee.y = __expf(v.y - m4);
        ee.z = __expf(v.z - m4);
        ee.w = __expf(v.w - m4);
        float s4 = ee.x + ee.y + ee.z + ee.w;
#pragma unroll
        for (int o = 16; o; o >>= 1)
            s4 += __shfl_xor_sync(0xffffffffu, s4, o);
        *(float4*)&ap[(size_t)q * S_ + k] = ee;
        if (lane == 0) {
            size_t idx = ((size_t)z * S_ + q) * 16 + kt;
            g_pm[idx] = m4;
            g_ps[idx] = s4;
        }
    }
}

// ---------------------------------------------------------------------------
// av_mma: per z, ctx[64(q) x 64(d)] = p @ V, K=2048 chunks of 64.
// Reads e_t, computes p = e_t * scl[ktile] (scl from per-tile partials),
// writes p back to attn (final output), converts p to bf16 hi/lo for mma.
// ---------------------------------------------------------------------------
static constexpr int AV_STG0 = 0;
static constexpr int AV_VT0  = 2 * 17408;                  // 34816
static constexpr int AV_AH   = AV_VT0 + 2 * 18432;         // 71680
static constexpr int AV_AL   = AV_AH + 9216;               // 80896
static constexpr int AV_SMEM = AV_AL + 9216;               // 90112

__global__ __launch_bounds__(256, 2) void av_mma(float* __restrict__ attn_g)
{
    extern __shared__ __align__(16) char sm[];
    uint32_t sb = s2u(sm);
    const int tid = threadIdx.x, lane = tid & 31, w = tid >> 5;
    const int wm = w >> 1, wn = w & 1;
    const int m0 = blockIdx.x * 64;
    const int z = blockIdx.y;
    const int lr = lane >> 2, lk = lane & 3, lc2 = (lane & 3) * 2;

    float* Ag = attn_g + (size_t)z * S_ * S_;
    const __nv_bfloat16* Vh = g_Vthi + (size_t)z * DK_ * S_;
    const __nv_bfloat16* Vl = g_Vtlo + (size_t)z * DK_ * S_;

    float acc[4][4];
#pragma unroll
    for (int i = 0; i < 4; ++i)
#pragma unroll
        for (int j = 0; j < 4; ++j) acc[i][j] = 0.f;

    // row stats for this thread's conversion row (cr fixed across chunks)
    const int cr = tid >> 2;                 // 0..63
    const int cj = (tid & 3) * 4;            // 0,4,8,12
    float scl[16];
    {
        const float* pmr = g_pm + ((size_t)z * S_ + m0 + cr) * 16;
        const float* psr = g_ps + ((size_t)z * S_ + m0 + cr) * 16;
        float pmv[16];
        float M = -3.4e38f;
#pragma unroll
        for (int t = 0; t < 16; ++t) { pmv[t] = pmr[t]; M = fmaxf(M, pmv[t]); }
        float ssum = 0.f;
#pragma unroll
        for (int t = 0; t < 16; ++t) scl[t] = __expf(pmv[t] - M);
#pragma unroll
        for (int t = 0; t < 16; ++t) ssum += psr[t] * scl[t];
        float inv = 1.0f / ssum;
#pragma unroll
        for (int t = 0; t < 16; ++t) scl[t] *= inv;
    }

    auto prefetch = [&](int c) {
        int k0 = c * 64;
        int bi = c & 1;
#pragma unroll
        for (int i = 0; i < 8; ++i) {
            int g = tid + i * 256;
            if (g < 1024) {
                int row = g >> 4, c16 = g & 15;
                uint32_t dst = sb + AV_STG0 + (uint32_t)bi * 17408 + row * 272 + c16 * 16;
                cp16(dst, Ag + (size_t)(m0 + row) * S_ + k0 + c16 * 4);
            } else {
                int g2 = g - 1024;
                int t = g2 >> 9, idx = g2 & 511;
                int row = idx >> 3, gc = idx & 7;
                uint32_t dst = sb + AV_VT0 + (uint32_t)bi * 18432 + (uint32_t)t * 9216 +
                               row * 144 + gc * 16;
                cp16(dst, (t ? Vl : Vh) + (size_t)row * S_ + k0 + gc * 8);
            }
        }
        cp_commit();
    };

    prefetch(0);
    for (int c = 0; c < 32; ++c) {
        if (c + 1 < 32) { prefetch(c + 1); cp_wait1(); }
        else            { cp_wait0(); }
        __syncthreads();
        // conversion: e_t -> p (single multiply), write p, split to bf16 hi/lo
        {
            const int k0 = c * 64;
            const float sc = scl[c >> 1];
            const float* st = (const float*)(sm + AV_STG0 + (c & 1) * 17408);
            uint32_t* AH = (uint32_t*)(sm + AV_AH);
            uint32_t* AL = (uint32_t*)(sm + AV_AL);
            float* prow = Ag + (size_t)(m0 + cr) * S_ + k0;
#pragma unroll
            for (int cc = 0; cc < 64; cc += 16) {
                int col = cc + cj;
                float4 v = *(const float4*)&st[cr * 68 + col];
                float4 p;
                p.x = v.x * sc; p.y = v.y * sc;
                p.z = v.z * sc; p.w = v.w * sc;
                *(float4*)&prow[col] = p;
                __nv_bfloat16 h0, h1, h2, h3, l0, l1, l2, l3;
                bsplit(p.x, h0, l0); bsplit(p.y, h1, l1);
                bsplit(p.z, h2, l2); bsplit(p.w, h3, l3);
                int wbase = cr * 36 + col / 2;
                AH[wbase]     = pack2(h0, h1);
                AH[wbase + 1] = pack2(h2, h3);
                AL[wbase]     = pack2(l0, l1);
                AL[wbase + 1] = pack2(l2, l3);
            }
        }
        __syncthreads();

        const uint32_t* AH = (const uint32_t*)(sm + AV_AH);
        const uint32_t* AL = (const uint32_t*)(sm + AV_AL);
        const uint32_t* VH = (const uint32_t*)(sm + AV_VT0 + (c & 1) * 18432);
        const uint32_t* VL = VH + 2304;
#pragma unroll
        for (int s = 0; s < 4; ++s) {
            uint32_t ah[4], al[4], bh[4][2], bl[4][2];
            {
                int r = wm * 16 + lr;
                int w0 = r * 36 + s * 8 + lk, w1 = (r + 8) * 36 + s * 8 + lk;
                ah[0] = AH[w0]; ah[1] = AH[w1];
                ah[2] = AH[w0 + 4]; ah[3] = AH[w1 + 4];
                al[0] = AL[w0]; al[1] = AL[w1];
                al[2] = AL[w0 + 4]; al[3] = AL[w1 + 4];
            }
#pragma unroll
            for (int nt = 0; nt < 4; ++nt) {
                int cc = wn * 32 + nt * 8 + lr;
                int wv = cc * 36 + s * 8 + lk;
                bh[nt][0] = VH[wv]; bh[nt][1] = VH[wv + 4];
                bl[nt][0] = VL[wv]; bl[nt][1] = VL[wv + 4];
            }
#pragma unroll
            for (int nt = 0; nt < 4; ++nt)
                mma_bf16(acc[nt], ah, bh[nt]);
#pragma unroll
            for (int nt = 0; nt < 4; ++nt)
                mma_bf16(acc[nt], ah, bl[nt]);
#pragma unroll
            for (int nt = 0; nt < 4; ++nt)
                mma_bf16(acc[nt], al, bh[nt]);
        }
        __syncthreads();
    }

    // epilogue: split ctx -> g_Xhi/g_Xlo slot 0 in (S,B,D) token layout
    const int bb = z >> 4, h = z & 15;
#pragma unroll
    for (int nt = 0; nt < 4; ++nt) {
        int d = wn * 32 + nt * 8 + lc2;
        const float* a = acc[nt];
#pragma unroll
        for (int hf = 0; hf < 2; ++hf) {
            int q = m0 + wm * 16 + lr + hf * 8;
            size_t o = ((size_t)q * B_ + bb) * D_ + h * DK_ + d;
            __nv_bfloat16 h0, h1, l0, l1;
            bsplit(a[hf * 2 + 0], h0, l0);
            bsplit(a[hf * 2 + 1], h1, l1);
            *(__nv_bfloat162*)&g_Xhi[o] = bf2(h0, h1);
            *(__nv_bfloat162*)&g_Xlo[o] = bf2(l0, l1);
        }
    }
}

// ---------------------------------------------------------------------------
extern "C" void kernel_launch(void* const* d_in, const int* in_sizes, int n_in,
                              void* d_out, int out_size)
{
    (void)in_sizes; (void)n_in; (void)out_size;
    const float* query = (const float*)d_in[0];
    const float* key   = (const float*)d_in[1];
    const float* value = (const float*)d_in[2];
    const int*   mask  = (const int*)d_in[3];
    const int*   kpm   = (const int*)d_in[4];
    const float* Wq    = (const float*)d_in[5];
    const float* Wk    = (const float*)d_in[6];
    const float* Wv    = (const float*)d_in[7];
    const float* Wo    = (const float*)d_in[8];
    const float* bo    = (const float*)d_in[9];

    float* out  = (float*)d_out;
    float* attn = out + (size_t)S_ * B_ * D_;   // tuple: (out, attn)

    cudaFuncSetAttribute(proj_mma,   cudaFuncAttributeMaxDynamicSharedMemorySize, PROJ_SMEM);
    cudaFuncSetAttribute(scores_mma, cudaFuncAttributeMaxDynamicSharedMemorySize, SC_SMEM);
    cudaFuncSetAttribute(av_mma,     cudaFuncAttributeMaxDynamicSharedMemorySize, AV_SMEM);

    mask_cmb<<<dim3(S_ * S_ / 1024, B_), 256>>>(mask, kpm);
    conv_split_x<<<dim3(R_ * D_ / 1024, 3), 256>>>(query, key, value);
    conv_split_w<<<dim3(D_ * D_ / 1024, 4), 256>>>(Wq, Wk, Wv, Wo);

    proj_mma<<<dim3(D_ / 128, R_ / 128, 3), 256, PROJ_SMEM>>>(nullptr, nullptr, 0);

    scores_mma<<<dim3(S_ / 128, S_ / 128, Z_), 256, SC_SMEM>>>(attn);
    av_mma<<<dim3(S_ / 64, Z_), 256, AV_SMEM>>>(attn);

    proj_mma<<<dim3(D_ / 128, R_ / 128, 1), 256, PROJ_SMEM>>>(bo, out, 3);
}